// round 2
// baseline (speedup 1.0000x reference)
#include <cuda_runtime.h>
#include <math.h>

#define S_LEN 128
#define BATCH 128
#define VOCAB 10000
#define EMB   512
#define HID   512

// ---------------- scratch (device globals: allocation-free) ----------------
__device__ float g_A0[S_LEN * BATCH * HID];   // emb[tok] @ W0x^T + b0, all steps
__device__ float g_H0[S_LEN * BATCH * HID];   // layer-0 hidden per step
__device__ float g_H1[S_LEN * BATCH * HID];   // layer-1 hidden per step
__device__ unsigned g_arrive;                 // grid barrier counter

// ---------------------------------------------------------------------------
// Generic NT tile GEMM accumulator.
// A: [tile_m rows][K], row stride lda (encoded in arows pointers)
// B: [tile_n rows][K], row stride ldb (encoded in brows pointers)
// acc[MM][MN] += A_tile @ B_tile^T
// 256 threads. tx in [0, TN/MN), ty in [0, TM/MM).
// Shared buffers sA (>= BK*(TM+4) floats), sB (>= BK*(TN+4) floats).
// ---------------------------------------------------------------------------
template <int TM, int TN, int BK, int MM, int MN>
__device__ __forceinline__ void tile_gemm(
    float acc[MM][MN],
    const float* const* arows,   // AF pointers: row base already includes k=0
    const float* const* brows,   // BF pointers
    float* sA, float* sB, int K, int tx, int ty)
{
    constexpr int AF  = (TM * BK) / 1024;   // float4 chunks per thread for A
    constexpr int BF  = (TN * BK) / 1024;
    constexpr int LDA = TM + 4;
    constexpr int LDB = TN + 4;
    const int tid = threadIdx.x;

    int ar[AF], ak[AF];
#pragma unroll
    for (int c = 0; c < AF; c++) { int f = 4 * (tid + c * 256); ar[c] = f / BK; ak[c] = f % BK; }
    int br[BF], bk[BF];
#pragma unroll
    for (int c = 0; c < BF; c++) { int f = 4 * (tid + c * 256); br[c] = f / BK; bk[c] = f % BK; }

    float4 pa[AF], pb[BF];
#pragma unroll
    for (int c = 0; c < AF; c++) pa[c] = *(const float4*)(arows[c] + ak[c]);
#pragma unroll
    for (int c = 0; c < BF; c++) pb[c] = *(const float4*)(brows[c] + bk[c]);

    const int nst = K / BK;
    for (int s = 0; s < nst; s++) {
        // stage prefetched regs -> smem (transposed: [k][row])
#pragma unroll
        for (int c = 0; c < AF; c++) {
            sA[(ak[c] + 0) * LDA + ar[c]] = pa[c].x;
            sA[(ak[c] + 1) * LDA + ar[c]] = pa[c].y;
            sA[(ak[c] + 2) * LDA + ar[c]] = pa[c].z;
            sA[(ak[c] + 3) * LDA + ar[c]] = pa[c].w;
        }
#pragma unroll
        for (int c = 0; c < BF; c++) {
            sB[(bk[c] + 0) * LDB + br[c]] = pb[c].x;
            sB[(bk[c] + 1) * LDB + br[c]] = pb[c].y;
            sB[(bk[c] + 2) * LDB + br[c]] = pb[c].z;
            sB[(bk[c] + 3) * LDB + br[c]] = pb[c].w;
        }
        __syncthreads();

        if (s + 1 < nst) {                       // prefetch next stage (hides LDG)
            int k0 = (s + 1) * BK;
#pragma unroll
            for (int c = 0; c < AF; c++) pa[c] = *(const float4*)(arows[c] + k0 + ak[c]);
#pragma unroll
            for (int c = 0; c < BF; c++) pb[c] = *(const float4*)(brows[c] + k0 + bk[c]);
        }

#pragma unroll
        for (int k = 0; k < BK; k++) {
            float a[MM], b[MN];
            if constexpr (MM % 4 == 0) {
#pragma unroll
                for (int i = 0; i < MM; i += 4) {
                    float4 v = *(const float4*)&sA[k * LDA + ty * MM + i];
                    a[i] = v.x; a[i + 1] = v.y; a[i + 2] = v.z; a[i + 3] = v.w;
                }
            } else {
#pragma unroll
                for (int i = 0; i < MM; i++) a[i] = sA[k * LDA + ty * MM + i];
            }
            if constexpr (MN % 4 == 0) {
#pragma unroll
                for (int j = 0; j < MN; j += 4) {
                    float4 v = *(const float4*)&sB[k * LDB + tx * MN + j];
                    b[j] = v.x; b[j + 1] = v.y; b[j + 2] = v.z; b[j + 3] = v.w;
                }
            } else {
#pragma unroll
                for (int j = 0; j < MN; j++) b[j] = sB[k * LDB + tx * MN + j];
            }
#pragma unroll
            for (int i = 0; i < MM; i++)
#pragma unroll
                for (int j = 0; j < MN; j++)
                    acc[i][j] = fmaf(a[i], b[j], acc[i][j]);
        }
        __syncthreads();
    }
}

// ---------------------------------------------------------------------------
// Big SGEMM: C[M,N] = A[M,K] @ B[N,K]^T + bias.  128x128x8 tiles, 8x8 micro.
// A == nullptr  -> read g_H1.   C == nullptr -> write g_A0.
// gather != nullptr -> A row m is A[gather[m]] (embedding lookup).
// ---------------------------------------------------------------------------
__global__ void __launch_bounds__(256) sgemm_big(
    const float* __restrict__ A, int lda, const int* __restrict__ gather,
    const float* __restrict__ B, int ldb, const float* __restrict__ bias,
    float* __restrict__ C, int ldc, int N, int K)
{
    __shared__ __align__(16) float sA[8 * 132];
    __shared__ __align__(16) float sB[8 * 132];

    const float* Ab = A ? A : g_H1;
    float*       Cb = C ? C : g_A0;

    const int bm = blockIdx.y, bn = blockIdx.x;
    const int tid = threadIdx.x, tx = tid % 16, ty = tid / 16;

    const float* arows[1];
    const float* brows[1];
    {
        int f = 4 * tid;
        int r = f / 8;                               // 0..127
        int m = bm * 128 + r;
        int arow = gather ? gather[m] : m;
        arows[0] = Ab + (size_t)arow * lda;
        int n = bn * 128 + r;
        if (n > N - 1) n = N - 1;                    // clamp (stores are masked)
        brows[0] = B + (size_t)n * ldb;
    }

    float acc[8][8];
#pragma unroll
    for (int i = 0; i < 8; i++)
#pragma unroll
        for (int j = 0; j < 8; j++) acc[i][j] = 0.0f;

    tile_gemm<128, 128, 8, 8, 8>(acc, arows, brows, sA, sB, K, tx, ty);

    // epilogue
    float bv[8];
    const int n0 = bn * 128 + tx * 8;
#pragma unroll
    for (int j = 0; j < 8; j++) bv[j] = (n0 + j < N) ? bias[n0 + j] : 0.0f;

#pragma unroll
    for (int i = 0; i < 8; i++) {
        size_t m = (size_t)(bm * 128 + ty * 8 + i);
        float* crow = Cb + m * (size_t)ldc;
#pragma unroll
        for (int j0 = 0; j0 < 8; j0 += 4) {
            int n = n0 + j0;
            if (n + 3 < N) {
                float4 v;
                v.x = acc[i][j0 + 0] + bv[j0 + 0];
                v.y = acc[i][j0 + 1] + bv[j0 + 1];
                v.z = acc[i][j0 + 2] + bv[j0 + 2];
                v.w = acc[i][j0 + 3] + bv[j0 + 3];
                *(float4*)(crow + n) = v;
            } else {
#pragma unroll
                for (int j = 0; j < 4; j++)
                    if (n + j < N) crow[n + j] = acc[i][j0 + j] + bv[j0 + j];
            }
        }
    }
}

// ---------------------------------------------------------------------------
// Persistent recurrent kernel. 96 CTAs (all co-resident on 148 SMs).
// Pipelined phases p = 0..128:
//   CTAs  0..31 : h0[p]  = tanh(g_A0[p]   + h0[p-1] @ W0h^T)          (p < 128)
//   CTAs 32..95 : h1[p-1]= tanh(b1 + h0[p-1] @ W1x^T + h1[p-2] @ W1h^T) (p >= 1)
// Software grid barrier between phases (monotone counter, reset kernel).
// ---------------------------------------------------------------------------
#define REC_CTAS 96

__global__ void reset_barrier_kernel() { g_arrive = 0u; }

__global__ void __launch_bounds__(256) rnn_recurrent(
    const float* __restrict__ hidden0,  // [2, B, H] initial hidden
    const float* __restrict__ W0,       // [H, 1024]
    const float* __restrict__ W1,       // [H, 1024]
    const float* __restrict__ b1)       // [H]
{
    __shared__ __align__(16) float sA[32 * 36];   // max TM=32
    __shared__ __align__(16) float sB[32 * 68];   // max TN=64

    const int bid = blockIdx.x;
    const int tid = threadIdx.x, tx = tid % 16, ty = tid / 16;
    const int BH = BATCH * HID;

    for (int p = 0; p <= S_LEN; p++) {
        if (bid < 32) {
            if (p < S_LEN) {
                const int t  = p;
                const int b0 = (bid >> 3) * 32;     // batch tile (32)
                const int h0 = (bid & 7) * 64;      // hid tile (64)
                float acc[2][4];
#pragma unroll
                for (int i = 0; i < 2; i++) {
                    int m = t * BATCH + b0 + ty * 2 + i;
                    float4 v = *(const float4*)&g_A0[(size_t)m * HID + h0 + tx * 4];
                    acc[i][0] = v.x; acc[i][1] = v.y; acc[i][2] = v.z; acc[i][3] = v.w;
                }
                const float* hp = (t == 0) ? hidden0 : (g_H0 + (size_t)(t - 1) * BH);
                const float* arows[1];
                const float* brows[2];
                {
                    int f = 4 * tid; int r = f / 32;
                    arows[0] = hp + (size_t)(b0 + r) * HID;
                }
#pragma unroll
                for (int c = 0; c < 2; c++) {
                    int f = 4 * (tid + c * 256); int r = f / 32;
                    brows[c] = W0 + (size_t)(h0 + r) * 1024 + 512;   // W0h part
                }
                tile_gemm<32, 64, 32, 2, 4>(acc, arows, brows, sA, sB, HID, tx, ty);
#pragma unroll
                for (int i = 0; i < 2; i++) {
                    int m = t * BATCH + b0 + ty * 2 + i;
                    float4 v;
                    v.x = tanhf(acc[i][0]); v.y = tanhf(acc[i][1]);
                    v.z = tanhf(acc[i][2]); v.w = tanhf(acc[i][3]);
                    *(float4*)&g_H0[(size_t)m * HID + h0 + tx * 4] = v;
                }
            }
        } else {
            if (p >= 1) {
                const int t  = p - 1;
                const int q  = bid - 32;
                const int b0 = (q >> 4) * 32;       // batch tile (32)
                const int h0 = (q & 15) * 32;       // hid tile (32)
                float acc[2][2];
#pragma unroll
                for (int i = 0; i < 2; i++)
#pragma unroll
                    for (int j = 0; j < 2; j++) acc[i][j] = b1[h0 + tx * 2 + j];

                const float* arows[1];
                const float* brows[1];
                int r0;
                { int f = 4 * tid; r0 = f / 32; }

                // part 1: h0[t] @ W1x^T
                arows[0] = g_H0 + (size_t)(t * BATCH + b0 + r0) * HID;
                brows[0] = W1 + (size_t)(h0 + r0) * 1024;
                tile_gemm<32, 32, 32, 2, 2>(acc, arows, brows, sA, sB, HID, tx, ty);

                // part 2: h1[t-1] @ W1h^T
                const float* hp1 = (t == 0) ? (hidden0 + BH) : (g_H1 + (size_t)(t - 1) * BH);
                arows[0] = hp1 + (size_t)(b0 + r0) * HID;
                brows[0] = W1 + (size_t)(h0 + r0) * 1024 + 512;
                tile_gemm<32, 32, 32, 2, 2>(acc, arows, brows, sA, sB, HID, tx, ty);

#pragma unroll
                for (int i = 0; i < 2; i++) {
                    int m = t * BATCH + b0 + ty * 2 + i;
#pragma unroll
                    for (int j = 0; j < 2; j++)
                        g_H1[(size_t)m * HID + h0 + tx * 2 + j] = tanhf(acc[i][j]);
                }
            }
        }

        // grid barrier (skip after final phase)
        if (p < S_LEN) {
            __syncthreads();
            __threadfence();
            if (tid == 0) {
                unsigned target = (unsigned)REC_CTAS * (unsigned)(p + 1);
                atomicAdd(&g_arrive, 1u);
                while (atomicAdd(&g_arrive, 0u) < target) { }
                __threadfence();
            }
            __syncthreads();
        }
    }
}

// ---------------------------------------------------------------------------
__global__ void copy_hidden_kernel(float* __restrict__ dst)
{
    const int BH = BATCH * HID;
    int i = blockIdx.x * blockDim.x + threadIdx.x;
    if (i < BH)           dst[i] = g_H0[(size_t)(S_LEN - 1) * BH + i];
    else if (i < 2 * BH)  dst[i] = g_H1[(size_t)(S_LEN - 1) * BH + (i - BH)];
}

// ---------------------------------------------------------------------------
extern "C" void kernel_launch(void* const* d_in, const int* in_sizes, int n_in,
                              void* d_out, int out_size)
{
    const int*   inputs = (const int*)  d_in[0];
    const float* hidden = (const float*)d_in[1];
    const float* W0     = (const float*)d_in[3];
    const float* b0     = (const float*)d_in[4];
    const float* W1     = (const float*)d_in[5];
    const float* b1     = (const float*)d_in[6];
    const float* Wout   = (const float*)d_in[7];
    const float* bout   = (const float*)d_in[8];
    const float* emb    = (const float*)d_in[2];
    float* out = (float*)d_out;

    // 1) reset grid-barrier counter
    reset_barrier_kernel<<<1, 1>>>();

    // 2) input projection for all steps: g_A0 = emb[tok] @ W0x^T + b0
    {
        dim3 grid(HID / 128, (S_LEN * BATCH) / 128);   // (4, 128)
        sgemm_big<<<grid, 256>>>(emb, EMB, inputs,
                                 W0, EMB + HID, b0,
                                 nullptr /*-> g_A0*/, HID, HID, EMB);
    }

    // 3) sequential recurrence (persistent, pipelined)
    rnn_recurrent<<<REC_CTAS, 256>>>(hidden, W0, W1, b1);

    // 4) logits = g_H1 @ Wout^T + bout  -> d_out
    {
        dim3 grid((VOCAB + 127) / 128, (S_LEN * BATCH) / 128);  // (79, 128)
        sgemm_big<<<grid, 256>>>(nullptr /*g_H1*/, HID, nullptr,
                                 Wout, HID, bout,
                                 out, VOCAB, VOCAB, HID);
    }

    // 5) final hidden state tail (if harness expects it)
    long long need = (long long)S_LEN * BATCH * VOCAB + 2LL * BATCH * HID;
    if ((long long)out_size >= need) {
        float* tail = out + (size_t)S_LEN * BATCH * VOCAB;
        copy_hidden_kernel<<<(2 * BATCH * HID) / 256, 256>>>(tail);
    }
}

// round 6
// speedup vs baseline: 2.2213x; 2.2213x over previous
#include <cuda_runtime.h>
#include <cuda_fp16.h>
#include <math.h>
#include <stdint.h>

#define S_LEN 128
#define BATCH 128
#define VOCAB 10000
#define NPAD  10240
#define EMB   512
#define HID   512

// ---------------- scratch (device globals: allocation-free) ----------------
__device__ float g_A0[S_LEN * BATCH * HID];   // emb[tok] @ W0x^T + b0, all steps
__device__ float g_H0[S_LEN * BATCH * HID];   // layer-0 hidden per step
__device__ float g_H1[S_LEN * BATCH * HID];   // layer-1 hidden per step
__device__ unsigned g_arrive;                 // grid barrier counter

// fp16 operands
__device__ __half g_embS [VOCAB * 1536];           // A-side split: [hi|hi|lo]
__device__ __half g_W0xS [HID * 1536];             // B-side split: [hi|lo|hi]
__device__ __half g_WoutH[NPAD * 512];             // B-side plain fp16, zero-padded
__device__ __half g_H1H  [S_LEN * BATCH * 512];    // A-side plain fp16

// =================== helpers ========================
__device__ __forceinline__ uint32_t smem_u32(const void* p) {
    uint32_t a;
    asm("{ .reg .u64 t; cvta.to.shared.u64 t, %1; cvt.u32.u64 %0, t; }" : "=r"(a) : "l"(p));
    return a;
}

#define CP_ASYNC16(dst, src) \
    asm volatile("cp.async.cg.shared.global [%0], [%1], 16;" :: "r"(dst), "l"(src) : "memory")
#define CP_COMMIT() asm volatile("cp.async.commit_group;" ::: "memory")
#define CP_WAIT1()  asm volatile("cp.async.wait_group 1;" ::: "memory")

#define LDMATRIX_X4(r0, r1, r2, r3, addr) \
    asm volatile("ldmatrix.sync.aligned.m8n8.x4.shared.b16 {%0,%1,%2,%3}, [%4];" \
                 : "=r"(r0), "=r"(r1), "=r"(r2), "=r"(r3) : "r"(addr))

#define MMA16816(c, a0, a1, a2, a3, b0, b1) \
    asm volatile("mma.sync.aligned.m16n8k16.row.col.f32.f16.f16.f32 " \
        "{%0,%1,%2,%3},{%4,%5,%6,%7},{%8,%9},{%10,%11,%12,%13};" \
        : "=f"((c)[0]), "=f"((c)[1]), "=f"((c)[2]), "=f"((c)[3]) \
        : "r"(a0), "r"(a1), "r"(a2), "r"(a3), "r"(b0), "r"(b1), \
          "f"((c)[0]), "f"((c)[1]), "f"((c)[2]), "f"((c)[3]))

// ======================= conversions ===========================
// plain fp16: dst[r][512]; rows >= src_rows zeroed.
__global__ void to_half_kernel(const float* __restrict__ src, int src_ld, int src_rows,
                               __half* __restrict__ dst, int dst_rows)
{
    int i = blockIdx.x * blockDim.x + threadIdx.x;
    if (i >= dst_rows * 512) return;
    int r = i >> 9, c = i & 511;
    float x = (r < src_rows) ? src[(size_t)r * src_ld + c] : 0.0f;
    dst[i] = __float2half_rn(x);
}

// fp16 split: dst[r][1536]. modeA -> [hi|hi|lo]; modeB -> [hi|lo|hi].
__global__ void split_half_kernel(const float* __restrict__ src, int src_ld, int src_rows,
                                  __half* __restrict__ dst, int dst_rows, int modeB)
{
    int i = blockIdx.x * blockDim.x + threadIdx.x;
    if (i >= dst_rows * 512) return;
    int r = i >> 9, c = i & 511;
    float x = (r < src_rows) ? src[(size_t)r * src_ld + c] : 0.0f;
    __half hi = __float2half_rn(x);
    __half lo = __float2half_rn(x - __half2float(hi));
    size_t base = (size_t)r * 1536;
    dst[base + c] = hi;
    if (modeB) { dst[base + 512 + c] = lo; dst[base + 1024 + c] = hi; }
    else       { dst[base + 512 + c] = hi; dst[base + 1024 + c] = lo; }
}

// ============= fp16 mma.sync GEMM: C = A @ B^T + bias (fp32 out) ===========
// A: [M,K] fp16 (rows optionally gathered), B: [Npad,K] fp16. K % 64 == 0.
// CTA tile 128x128; K consumed in stages of 64. 8 warps -> 64x32 warp tiles.
#define GEMM_SMEM (4 * 128 * 128)   // 2 bufs * (A 16KB + B 16KB) = 64KB

__global__ void __launch_bounds__(256) gemm_fp16_mma(
    const __half* __restrict__ A,
    const int* __restrict__ gather,
    const __half* __restrict__ B,
    const float* __restrict__ bias,
    float* __restrict__ C, int ldc, int Nreal, int K)
{
    extern __shared__ __align__(1024) char smem[];
    const uint32_t sbase = smem_u32(smem);
    const uint32_t offA[2] = { 0u, 16384u };
    const uint32_t offB[2] = { 32768u, 49152u };

    const int tid  = threadIdx.x;
    const int lane = tid & 31;
    const int w    = tid >> 5;
    const int wm   = w >> 2;        // 0..1  (64-row slab)
    const int wn   = w & 3;         // 0..3  (32-col slab)
    const int m0   = blockIdx.y * 128;
    const int n0   = blockIdx.x * 128;

    // ---- load slots: 4 chunks (16B) per thread per operand per stage ----
    // stage = 64 halves/row = 8 chunks/row; 128 rows * 8 = 1024 chunks = 256thr*4
    const __half* asrc[4]; uint32_t adst[4];
    const __half* bsrc[4]; uint32_t bdst[4];
#pragma unroll
    for (int j = 0; j < 4; j++) {
        int id = tid + j * 256;          // 0..1023
        int r = id >> 3, c = id & 7;     // row 0..127, chunk 0..7
        int row = m0 + r;
        if (gather) row = gather[row];
        asrc[j] = A + (size_t)row * K + c * 8;
        adst[j] = (uint32_t)(r * 128 + ((c ^ (r & 7)) << 4));
        bsrc[j] = B + (size_t)(n0 + r) * K + c * 8;
        bdst[j] = adst[j];
    }

    float acc[4][4][4];
#pragma unroll
    for (int i = 0; i < 4; i++)
#pragma unroll
        for (int j = 0; j < 4; j++)
#pragma unroll
            for (int k = 0; k < 4; k++) acc[i][j][k] = 0.0f;

    // ---- prologue: stage 0 ----
#pragma unroll
    for (int j = 0; j < 4; j++) {
        CP_ASYNC16(sbase + offA[0] + adst[j], asrc[j]);
        CP_ASYNC16(sbase + offB[0] + bdst[j], bsrc[j]);
    }
    CP_COMMIT();

    const int nst = K >> 6;
#pragma unroll 1
    for (int s = 0; s < nst; s++) {
        if (s + 1 < nst) {
            const int nb = (s + 1) & 1;
            const int ke = (s + 1) * 64;
#pragma unroll
            for (int j = 0; j < 4; j++) {
                CP_ASYNC16(sbase + offA[nb] + adst[j], asrc[j] + ke);
                CP_ASYNC16(sbase + offB[nb] + bdst[j], bsrc[j] + ke);
            }
        }
        CP_COMMIT();
        CP_WAIT1();
        __syncthreads();

        const uint32_t aBase = sbase + offA[s & 1];
        const uint32_t bBase = sbase + offB[s & 1];

#pragma unroll
        for (int kk = 0; kk < 4; kk++) {
            uint32_t aR[4][4], bR[4][2];
#pragma unroll
            for (int t = 0; t < 4; t++) {
                int row = wm * 64 + t * 16 + (lane & 15);
                int c   = kk * 2 + (lane >> 4);
                uint32_t ad = aBase + (uint32_t)(row * 128 + ((c ^ (row & 7)) << 4));
                LDMATRIX_X4(aR[t][0], aR[t][1], aR[t][2], aR[t][3], ad);
            }
#pragma unroll
            for (int p = 0; p < 2; p++) {
                int nrow = wn * 32 + p * 16 + (lane & 7) + ((lane >> 4) << 3);
                int c    = kk * 2 + ((lane >> 3) & 1);
                uint32_t bd = bBase + (uint32_t)(nrow * 128 + ((c ^ (nrow & 7)) << 4));
                uint32_t r0, r1, r2, r3;
                LDMATRIX_X4(r0, r1, r2, r3, bd);
                bR[p * 2 + 0][0] = r0; bR[p * 2 + 0][1] = r1;
                bR[p * 2 + 1][0] = r2; bR[p * 2 + 1][1] = r3;
            }
#pragma unroll
            for (int i = 0; i < 4; i++)
#pragma unroll
                for (int j = 0; j < 4; j++)
                    MMA16816(acc[i][j], aR[i][0], aR[i][1], aR[i][2], aR[i][3],
                             bR[j][0], bR[j][1]);
        }
        __syncthreads();
    }

    // ---- epilogue: direct stores (float2 per lane) ----
    const int g  = lane >> 2;
    const int tg = lane & 3;
#pragma unroll
    for (int j = 0; j < 4; j++) {
        int col = n0 + wn * 32 + j * 8 + tg * 2;
        if (col >= Nreal) continue;                 // Nreal % 8 == 0
        float2 bv = *(const float2*)&bias[col];
#pragma unroll
        for (int i = 0; i < 4; i++) {
            int r0 = m0 + wm * 64 + i * 16 + g;
            float2 v0 = make_float2(acc[i][j][0] + bv.x, acc[i][j][1] + bv.y);
            float2 v1 = make_float2(acc[i][j][2] + bv.x, acc[i][j][3] + bv.y);
            *(float2*)&C[(size_t)r0 * ldc + col]       = v0;
            *(float2*)&C[(size_t)(r0 + 8) * ldc + col] = v1;
        }
    }
}

// ---------------------------------------------------------------------------
// fp32 tile GEMM accumulator (recurrent kernel — unchanged, proven passing)
// ---------------------------------------------------------------------------
template <int TM, int TN, int BK, int MM, int MN>
__device__ __forceinline__ void tile_gemm(
    float acc[MM][MN],
    const float* const* arows, const float* const* brows,
    float* sA, float* sB, int K, int tx, int ty)
{
    constexpr int AF  = (TM * BK) / 1024;
    constexpr int BF  = (TN * BK) / 1024;
    constexpr int LDA = TM + 4;
    constexpr int LDB = TN + 4;
    const int tid = threadIdx.x;

    int ar[AF], ak[AF];
#pragma unroll
    for (int c = 0; c < AF; c++) { int f = 4 * (tid + c * 256); ar[c] = f / BK; ak[c] = f % BK; }
    int br[BF], bk[BF];
#pragma unroll
    for (int c = 0; c < BF; c++) { int f = 4 * (tid + c * 256); br[c] = f / BK; bk[c] = f % BK; }

    float4 pa[AF], pb[BF];
#pragma unroll
    for (int c = 0; c < AF; c++) pa[c] = *(const float4*)(arows[c] + ak[c]);
#pragma unroll
    for (int c = 0; c < BF; c++) pb[c] = *(const float4*)(brows[c] + bk[c]);

    const int nst = K / BK;
    for (int s = 0; s < nst; s++) {
#pragma unroll
        for (int c = 0; c < AF; c++) {
            sA[(ak[c] + 0) * LDA + ar[c]] = pa[c].x;
            sA[(ak[c] + 1) * LDA + ar[c]] = pa[c].y;
            sA[(ak[c] + 2) * LDA + ar[c]] = pa[c].z;
            sA[(ak[c] + 3) * LDA + ar[c]] = pa[c].w;
        }
#pragma unroll
        for (int c = 0; c < BF; c++) {
            sB[(bk[c] + 0) * LDB + br[c]] = pb[c].x;
            sB[(bk[c] + 1) * LDB + br[c]] = pb[c].y;
            sB[(bk[c] + 2) * LDB + br[c]] = pb[c].z;
            sB[(bk[c] + 3) * LDB + br[c]] = pb[c].w;
        }
        __syncthreads();

        if (s + 1 < nst) {
            int k0 = (s + 1) * BK;
#pragma unroll
            for (int c = 0; c < AF; c++) pa[c] = *(const float4*)(arows[c] + k0 + ak[c]);
#pragma unroll
            for (int c = 0; c < BF; c++) pb[c] = *(const float4*)(brows[c] + k0 + bk[c]);
        }

#pragma unroll
        for (int k = 0; k < BK; k++) {
            float a[MM], b[MN];
#pragma unroll
            for (int i = 0; i < MM; i++) a[i] = sA[k * LDA + ty * MM + i];
#pragma unroll
            for (int j = 0; j < MN; j++) b[j] = sB[k * LDB + tx * MN + j];
#pragma unroll
            for (int i = 0; i < MM; i++)
#pragma unroll
                for (int j = 0; j < MN; j++)
                    acc[i][j] = fmaf(a[i], b[j], acc[i][j]);
        }
        __syncthreads();
    }
}

#define REC_CTAS 96

__global__ void reset_barrier_kernel() { g_arrive = 0u; }

__global__ void __launch_bounds__(256) rnn_recurrent(
    const float* __restrict__ hidden0,
    const float* __restrict__ W0,
    const float* __restrict__ W1,
    const float* __restrict__ b1)
{
    __shared__ __align__(16) float sA[32 * 36];
    __shared__ __align__(16) float sB[32 * 68];

    const int bid = blockIdx.x;
    const int tid = threadIdx.x, tx = tid % 16, ty = tid / 16;
    const int BH = BATCH * HID;

    for (int p = 0; p <= S_LEN; p++) {
        if (bid < 32) {
            if (p < S_LEN) {
                const int t  = p;
                const int b0 = (bid >> 3) * 32;
                const int h0 = (bid & 7) * 64;
                float acc[2][4];
#pragma unroll
                for (int i = 0; i < 2; i++) {
                    int m = t * BATCH + b0 + ty * 2 + i;
                    float4 v = *(const float4*)&g_A0[(size_t)m * HID + h0 + tx * 4];
                    acc[i][0] = v.x; acc[i][1] = v.y; acc[i][2] = v.z; acc[i][3] = v.w;
                }
                const float* hp = (t == 0) ? hidden0 : (g_H0 + (size_t)(t - 1) * BH);
                const float* arows[1];
                const float* brows[2];
                {
                    int f = 4 * tid; int r = f / 32;
                    arows[0] = hp + (size_t)(b0 + r) * HID;
                }
#pragma unroll
                for (int c = 0; c < 2; c++) {
                    int f = 4 * (tid + c * 256); int r = f / 32;
                    brows[c] = W0 + (size_t)(h0 + r) * 1024 + 512;
                }
                tile_gemm<32, 64, 32, 2, 4>(acc, arows, brows, sA, sB, HID, tx, ty);
#pragma unroll
                for (int i = 0; i < 2; i++) {
                    int m = t * BATCH + b0 + ty * 2 + i;
                    float4 v;
                    v.x = tanhf(acc[i][0]); v.y = tanhf(acc[i][1]);
                    v.z = tanhf(acc[i][2]); v.w = tanhf(acc[i][3]);
                    *(float4*)&g_H0[(size_t)m * HID + h0 + tx * 4] = v;
                }
            }
        } else {
            if (p >= 1) {
                const int t  = p - 1;
                const int q  = bid - 32;
                const int b0 = (q >> 4) * 32;
                const int h0 = (q & 15) * 32;
                float acc[2][2];
#pragma unroll
                for (int i = 0; i < 2; i++)
#pragma unroll
                    for (int j = 0; j < 2; j++) acc[i][j] = b1[h0 + tx * 2 + j];

                const float* arows[1];
                const float* brows[1];
                int r0;
                { int f = 4 * tid; r0 = f / 32; }

                arows[0] = g_H0 + (size_t)(t * BATCH + b0 + r0) * HID;
                brows[0] = W1 + (size_t)(h0 + r0) * 1024;
                tile_gemm<32, 32, 32, 2, 2>(acc, arows, brows, sA, sB, HID, tx, ty);

                const float* hp1 = (t == 0) ? (hidden0 + BH) : (g_H1 + (size_t)(t - 1) * BH);
                arows[0] = hp1 + (size_t)(b0 + r0) * HID;
                brows[0] = W1 + (size_t)(h0 + r0) * 1024 + 512;
                tile_gemm<32, 32, 32, 2, 2>(acc, arows, brows, sA, sB, HID, tx, ty);

#pragma unroll
                for (int i = 0; i < 2; i++) {
                    int m = t * BATCH + b0 + ty * 2 + i;
#pragma unroll
                    for (int j = 0; j < 2; j++)
                        g_H1[(size_t)m * HID + h0 + tx * 2 + j] = tanhf(acc[i][j]);
                }
            }
        }

        if (p < S_LEN) {
            __syncthreads();
            __threadfence();
            if (tid == 0) {
                unsigned target = (unsigned)REC_CTAS * (unsigned)(p + 1);
                atomicAdd(&g_arrive, 1u);
                while (atomicAdd(&g_arrive, 0u) < target) { }
                __threadfence();
            }
            __syncthreads();
        }
    }
}

// ---------------------------------------------------------------------------
__global__ void copy_hidden_kernel(float* __restrict__ dst)
{
    const int BH = BATCH * HID;
    int i = blockIdx.x * blockDim.x + threadIdx.x;
    if (i < BH)           dst[i] = g_H0[(size_t)(S_LEN - 1) * BH + i];
    else if (i < 2 * BH)  dst[i] = g_H1[(size_t)(S_LEN - 1) * BH + (i - BH)];
}

// ---------------------------------------------------------------------------
extern "C" void kernel_launch(void* const* d_in, const int* in_sizes, int n_in,
                              void* d_out, int out_size)
{
    const int*   inputs = (const int*)  d_in[0];
    const float* hidden = (const float*)d_in[1];
    const float* emb    = (const float*)d_in[2];
    const float* W0     = (const float*)d_in[3];
    const float* b0     = (const float*)d_in[4];
    const float* W1     = (const float*)d_in[5];
    const float* b1     = (const float*)d_in[6];
    const float* Wout   = (const float*)d_in[7];
    const float* bout   = (const float*)d_in[8];
    float* out = (float*)d_out;

    cudaFuncSetAttribute(gemm_fp16_mma, cudaFuncAttributeMaxDynamicSharedMemorySize,
                         GEMM_SMEM);

    __half *embS, *w0xS, *woutH, *h1H;
    float *a0, *h1;
    cudaGetSymbolAddress((void**)&embS,  g_embS);
    cudaGetSymbolAddress((void**)&w0xS,  g_W0xS);
    cudaGetSymbolAddress((void**)&woutH, g_WoutH);
    cudaGetSymbolAddress((void**)&h1H,   g_H1H);
    cudaGetSymbolAddress((void**)&a0,    g_A0);
    cudaGetSymbolAddress((void**)&h1,    g_H1);

    // 1) grid-barrier reset
    reset_barrier_kernel<<<1, 1>>>();

    // 2) operand conversions
    //    emb/W0x: fp16 3-term split (feeds recurrence -> needs ~fp32 accuracy)
    split_half_kernel<<<(VOCAB * 512 + 255) / 256, 256>>>(emb, 512,  VOCAB, embS, VOCAB, 0);
    split_half_kernel<<<(HID   * 512 + 255) / 256, 256>>>(W0,  1024, HID,   w0xS, HID,   1);
    //    Wout: plain fp16 (final output, no amplification)
    to_half_kernel<<<(NPAD * 512 + 255) / 256, 256>>>(Wout, 512, VOCAB, woutH, NPAD);

    // 3) input projection (HMMA, split K=1536): g_A0 = emb[tok] @ W0x^T + b0
    {
        dim3 grid(HID / 128, (S_LEN * BATCH) / 128);   // (4, 128)
        gemm_fp16_mma<<<grid, 256, GEMM_SMEM>>>(embS, inputs, w0xS, b0, a0, HID, HID, 1536);
    }

    // 4) sequential recurrence (persistent, pipelined, fp32)
    rnn_recurrent<<<REC_CTAS, 256>>>(hidden, W0, W1, b1);

    // 5) H1 -> fp16
    to_half_kernel<<<(S_LEN * BATCH * 512 + 255) / 256, 256>>>(h1, 512, S_LEN * BATCH,
                                                               h1H, S_LEN * BATCH);

    // 6) logits = H1 @ Wout^T + bout (HMMA, K=512)
    {
        dim3 grid(NPAD / 128, (S_LEN * BATCH) / 128);  // (80, 128)
        gemm_fp16_mma<<<grid, 256, GEMM_SMEM>>>(h1H, nullptr, woutH, bout, out, VOCAB,
                                                VOCAB, 512);
    }

    // 7) final hidden tail if the output buffer carries it
    long long need = (long long)S_LEN * BATCH * VOCAB + 2LL * BATCH * HID;
    if ((long long)out_size >= need) {
        float* tail = out + (size_t)S_LEN * BATCH * VOCAB;
        copy_hidden_kernel<<<(2 * BATCH * HID) / 256, 256>>>(tail);
    }
}

// round 7
// speedup vs baseline: 3.0842x; 1.3884x over previous
#include <cuda_runtime.h>
#include <cuda_fp16.h>
#include <math.h>
#include <stdint.h>

#define S_LEN 128
#define BATCH 128
#define VOCAB 10000
#define NPAD  10240
#define EMB   512
#define HID   512

// ---------------- scratch (device globals: allocation-free) ----------------
__device__ float g_A0[S_LEN * BATCH * HID];   // emb[tok] @ W0x^T + b0, all steps
__device__ float g_H0[S_LEN * BATCH * HID];   // layer-0 hidden (only t=127 written)
__device__ float g_H1[S_LEN * BATCH * HID];   // layer-1 hidden (only t=127 written)
__device__ unsigned g_arrive;                 // grid barrier counter

// fp16 operands
__device__ __half g_embS [VOCAB * 1536];           // A-side split: [hi|hi|lo]
__device__ __half g_W0xS [HID * 1536];             // B-side split: [hi|lo|hi]
__device__ __half g_WoutH[NPAD * 512];             // B-side plain fp16, zero-padded
__device__ __half g_H1H  [S_LEN * BATCH * 512];    // A-side plain fp16 (logits input)

// recurrence split operands
__device__ __half g_W0hS[HID * 1536];              // B-split of W0[:,512:1024]
__device__ __half g_W1S [HID * 3072];              // B-split of [W1x | W1h]
__device__ __half g_L0A [(S_LEN + 1) * BATCH * 1536]; // h0[t-1] split [hi|hi|lo]
__device__ __half g_L1A [(S_LEN + 1) * BATCH * 3072]; // [h0[t] hi|hi|lo | h1[t-1] hi|hi|lo]

// =================== helpers ========================
__device__ __forceinline__ uint32_t smem_u32(const void* p) {
    uint32_t a;
    asm("{ .reg .u64 t; cvta.to.shared.u64 t, %1; cvt.u32.u64 %0, t; }" : "=r"(a) : "l"(p));
    return a;
}

#define CP_ASYNC16(dst, src) \
    asm volatile("cp.async.cg.shared.global [%0], [%1], 16;" :: "r"(dst), "l"(src) : "memory")
#define CP_COMMIT() asm volatile("cp.async.commit_group;" ::: "memory")
#define CP_WAIT1()  asm volatile("cp.async.wait_group 1;" ::: "memory")
#define CP_WAIT3()  asm volatile("cp.async.wait_group 3;" ::: "memory")

#define LDMATRIX_X4(r0, r1, r2, r3, addr) \
    asm volatile("ldmatrix.sync.aligned.m8n8.x4.shared.b16 {%0,%1,%2,%3}, [%4];" \
                 : "=r"(r0), "=r"(r1), "=r"(r2), "=r"(r3) : "r"(addr))

#define MMA16816(c, a0, a1, a2, a3, b0, b1) \
    asm volatile("mma.sync.aligned.m16n8k16.row.col.f32.f16.f16.f32 " \
        "{%0,%1,%2,%3},{%4,%5,%6,%7},{%8,%9},{%10,%11,%12,%13};" \
        : "=f"((c)[0]), "=f"((c)[1]), "=f"((c)[2]), "=f"((c)[3]) \
        : "r"(a0), "r"(a1), "r"(a2), "r"(a3), "r"(b0), "r"(b1), \
          "f"((c)[0]), "f"((c)[1]), "f"((c)[2]), "f"((c)[3]))

// ======================= conversions ===========================
__global__ void to_half_kernel(const float* __restrict__ src, int src_ld, int src_rows,
                               __half* __restrict__ dst, int dst_rows)
{
    int i = blockIdx.x * blockDim.x + threadIdx.x;
    if (i >= dst_rows * 512) return;
    int r = i >> 9, c = i & 511;
    float x = (r < src_rows) ? src[(size_t)r * src_ld + c] : 0.0f;
    dst[i] = __float2half_rn(x);
}

// split with arbitrary dst row stride + offset. modeB -> [hi|lo|hi]; else [hi|hi|lo].
__global__ void split_half_ld(const float* __restrict__ src, int src_ld, int src_rows,
                              __half* __restrict__ dst, long long dst_ld, long long dst_off,
                              int dst_rows, int modeB)
{
    int i = blockIdx.x * blockDim.x + threadIdx.x;
    if (i >= dst_rows * 512) return;
    int r = i >> 9, c = i & 511;
    float x = (r < src_rows) ? src[(size_t)r * src_ld + c] : 0.0f;
    __half hi = __float2half_rn(x);
    __half lo = __float2half_rn(x - __half2float(hi));
    size_t base = (size_t)r * dst_ld + dst_off;
    dst[base + c] = hi;
    if (modeB) { dst[base + 512 + c] = lo; dst[base + 1024 + c] = hi; }
    else       { dst[base + 512 + c] = hi; dst[base + 1024 + c] = lo; }
}

// ============= fp16 mma.sync GEMM: C = A @ B^T + bias (fp32 out) ===========
#define GEMM_SMEM (4 * 128 * 128)   // 64KB

__global__ void __launch_bounds__(256) gemm_fp16_mma(
    const __half* __restrict__ A,
    const int* __restrict__ gather,
    const __half* __restrict__ B,
    const float* __restrict__ bias,
    float* __restrict__ C, int ldc, int Nreal, int K)
{
    extern __shared__ __align__(1024) char smem[];
    const uint32_t sbase = smem_u32(smem);
    const uint32_t offA[2] = { 0u, 16384u };
    const uint32_t offB[2] = { 32768u, 49152u };

    const int tid  = threadIdx.x;
    const int lane = tid & 31;
    const int w    = tid >> 5;
    const int wm   = w >> 2;
    const int wn   = w & 3;
    const int m0   = blockIdx.y * 128;
    const int n0   = blockIdx.x * 128;

    const __half* asrc[4]; uint32_t adst[4];
    const __half* bsrc[4]; uint32_t bdst[4];
#pragma unroll
    for (int j = 0; j < 4; j++) {
        int id = tid + j * 256;
        int r = id >> 3, c = id & 7;
        int row = m0 + r;
        if (gather) row = gather[row];
        asrc[j] = A + (size_t)row * K + c * 8;
        adst[j] = (uint32_t)(r * 128 + ((c ^ (r & 7)) << 4));
        bsrc[j] = B + (size_t)(n0 + r) * K + c * 8;
        bdst[j] = adst[j];
    }

    float acc[4][4][4];
#pragma unroll
    for (int i = 0; i < 4; i++)
#pragma unroll
        for (int j = 0; j < 4; j++)
#pragma unroll
            for (int k = 0; k < 4; k++) acc[i][j][k] = 0.0f;

#pragma unroll
    for (int j = 0; j < 4; j++) {
        CP_ASYNC16(sbase + offA[0] + adst[j], asrc[j]);
        CP_ASYNC16(sbase + offB[0] + bdst[j], bsrc[j]);
    }
    CP_COMMIT();

    const int nst = K >> 6;
#pragma unroll 1
    for (int s = 0; s < nst; s++) {
        if (s + 1 < nst) {
            const int nb = (s + 1) & 1;
            const int ke = (s + 1) * 64;
#pragma unroll
            for (int j = 0; j < 4; j++) {
                CP_ASYNC16(sbase + offA[nb] + adst[j], asrc[j] + ke);
                CP_ASYNC16(sbase + offB[nb] + bdst[j], bsrc[j] + ke);
            }
        }
        CP_COMMIT();
        CP_WAIT1();
        __syncthreads();

        const uint32_t aBase = sbase + offA[s & 1];
        const uint32_t bBase = sbase + offB[s & 1];

#pragma unroll
        for (int kk = 0; kk < 4; kk++) {
            uint32_t aR[4][4], bR[4][2];
#pragma unroll
            for (int t = 0; t < 4; t++) {
                int row = wm * 64 + t * 16 + (lane & 15);
                int c   = kk * 2 + (lane >> 4);
                uint32_t ad = aBase + (uint32_t)(row * 128 + ((c ^ (row & 7)) << 4));
                LDMATRIX_X4(aR[t][0], aR[t][1], aR[t][2], aR[t][3], ad);
            }
#pragma unroll
            for (int p = 0; p < 2; p++) {
                int nrow = wn * 32 + p * 16 + (lane & 7) + ((lane >> 4) << 3);
                int c    = kk * 2 + ((lane >> 3) & 1);
                uint32_t bd = bBase + (uint32_t)(nrow * 128 + ((c ^ (nrow & 7)) << 4));
                uint32_t r0, r1, r2, r3;
                LDMATRIX_X4(r0, r1, r2, r3, bd);
                bR[p * 2 + 0][0] = r0; bR[p * 2 + 0][1] = r1;
                bR[p * 2 + 1][0] = r2; bR[p * 2 + 1][1] = r3;
            }
#pragma unroll
            for (int i = 0; i < 4; i++)
#pragma unroll
                for (int j = 0; j < 4; j++)
                    MMA16816(acc[i][j], aR[i][0], aR[i][1], aR[i][2], aR[i][3],
                             bR[j][0], bR[j][1]);
        }
        __syncthreads();
    }

    const int g  = lane >> 2;
    const int tg = lane & 3;
#pragma unroll
    for (int j = 0; j < 4; j++) {
        int col = n0 + wn * 32 + j * 8 + tg * 2;
        if (col >= Nreal) continue;
        float2 bv = *(const float2*)&bias[col];
#pragma unroll
        for (int i = 0; i < 4; i++) {
            int r0 = m0 + wm * 64 + i * 16 + g;
            float2 v0 = make_float2(acc[i][j][0] + bv.x, acc[i][j][1] + bv.y);
            float2 v1 = make_float2(acc[i][j][2] + bv.x, acc[i][j][3] + bv.y);
            *(float2*)&C[(size_t)r0 * ldc + col]       = v0;
            *(float2*)&C[(size_t)(r0 + 8) * ldc + col] = v1;
        }
    }
}

// ===================== tensor-core recurrent kernel ========================
// 96 CTAs (all resident). L0 (bid 0..31): 32 CTAs, tile 64x32, K=1536.
// L1 (bid 32..95): 64 CTAs, tile 64x16, K=3072. W slices smem-resident.
#define REC_CTAS 96
#define REC_AOFF (96 * 1024)
#define REC_SMEM (96 * 1024 + 4 * 8192)   // 131072

__global__ void reset_barrier_kernel() { g_arrive = 0u; }

__global__ void __launch_bounds__(256) rnn_rec_tc(const float* __restrict__ b1)
{
    extern __shared__ __align__(1024) char smem[];
    const uint32_t sbase = smem_u32(smem);
    const int bid  = blockIdx.x;
    const int tid  = threadIdx.x;
    const int lane = tid & 31;
    const int w    = tid >> 5;
    const int wm   = w >> 1;        // 0..3 (m16 slab)
    const int wn   = w & 1;         // 0..1
    const bool isL0 = (bid < 32);

    int nbase, mb, AK, NST, WSTB, wrows;
    const __half* Wsrc;
    const __half* Abase0;
    if (isL0) {
        int ms = bid & 1, nt = bid >> 1;
        nbase = nt * 32; mb = ms * 64;
        AK = 1536; NST = 24; WSTB = 4096; wrows = 32;
        Wsrc = g_W0hS; Abase0 = g_L0A;
    } else {
        int q = bid - 32;
        int ms = q & 1, nt = q >> 1;
        nbase = nt * 16; mb = ms * 64;
        AK = 3072; NST = 48; WSTB = 2048; wrows = 16;
        Wsrc = g_W1S; Abase0 = g_L1A;
    }

    // ---- load W slice resident (per-stage 128B-row swizzled blocks) ----
    {
        const int per = wrows * 8;                 // chunks per stage
        const int chunks = NST * per;              // 6144 for both layers
        for (int id = tid; id < chunks; id += 256) {
            int s = id / per, rem = id % per;
            int r = rem >> 3, c8 = rem & 7;
            uint32_t off = (uint32_t)(s * WSTB + r * 128 + ((c8 ^ (r & 7)) << 4));
            const __half* src = Wsrc + (size_t)(nbase + r) * AK + s * 64 + c8 * 8;
            *(uint4*)(smem + off) = *(const uint4*)src;
        }
    }
    __syncthreads();

    // per-thread A-load slots (2 x 16B chunks per 8KB stage: 64 rows x 8 chunks)
    int ar_[2], ac8_[2]; uint32_t adst_[2];
#pragma unroll
    for (int j = 0; j < 2; j++) {
        int id = tid + j * 256;
        ar_[j] = id >> 3; ac8_[j] = id & 7;
        adst_[j] = (uint32_t)(ar_[j] * 128 + ((ac8_[j] ^ (ar_[j] & 7)) << 4));
    }

#pragma unroll 1
    for (int p = 0; p <= S_LEN; p++) {
        const bool active = isL0 ? (p < S_LEN) : (p >= 1);
        if (active) {
            const int t = isL0 ? p : (p - 1);
            const __half* Ab = Abase0 + (size_t)t * BATCH * AK;
            const __half* aptr[2];
#pragma unroll
            for (int j = 0; j < 2; j++)
                aptr[j] = Ab + (size_t)(mb + ar_[j]) * AK + ac8_[j] * 8;

            float acc[2][4];
#pragma unroll
            for (int i = 0; i < 2; i++)
#pragma unroll
                for (int k = 0; k < 4; k++) acc[i][k] = 0.0f;

#define REC_ISSUE(s) do {                                                  \
    uint32_t buf = sbase + REC_AOFF + (((s) & 3) << 13);                   \
    CP_ASYNC16(buf + adst_[0], aptr[0] + (s) * 64);                        \
    CP_ASYNC16(buf + adst_[1], aptr[1] + (s) * 64);                        \
} while (0)

            REC_ISSUE(0); CP_COMMIT();
            REC_ISSUE(1); CP_COMMIT();
            REC_ISSUE(2); CP_COMMIT();

#pragma unroll 1
            for (int s = 0; s < NST; s++) {
                if (s + 3 < NST) REC_ISSUE(s + 3);
                CP_COMMIT();
                CP_WAIT3();
                __syncthreads();

                const uint32_t aB = sbase + REC_AOFF + ((s & 3) << 13);
                const uint32_t wB = sbase + s * WSTB;

                if (isL0) {
#pragma unroll
                    for (int kk = 0; kk < 4; kk++) {
                        uint32_t a0, a1, a2, a3, b0, b1r, b2, b3;
                        int arow = wm * 16 + (lane & 15);
                        int ac   = kk * 2 + (lane >> 4);
                        LDMATRIX_X4(a0, a1, a2, a3,
                                    aB + (uint32_t)(arow * 128 + ((ac ^ (arow & 7)) << 4)));
                        int brow = wn * 16 + (lane & 7) + ((lane >> 4) << 3);
                        int bc   = kk * 2 + ((lane >> 3) & 1);
                        LDMATRIX_X4(b0, b1r, b2, b3,
                                    wB + (uint32_t)(brow * 128 + ((bc ^ (brow & 7)) << 4)));
                        MMA16816(acc[0], a0, a1, a2, a3, b0, b1r);
                        MMA16816(acc[1], a0, a1, a2, a3, b2, b3);
                    }
                } else {
#pragma unroll
                    for (int kk2 = 0; kk2 < 2; kk2++) {
                        uint32_t aR[2][4];
#pragma unroll
                        for (int u = 0; u < 2; u++) {
                            int kk = kk2 * 2 + u;
                            int arow = wm * 16 + (lane & 15);
                            int ac   = kk * 2 + (lane >> 4);
                            LDMATRIX_X4(aR[u][0], aR[u][1], aR[u][2], aR[u][3],
                                        aB + (uint32_t)(arow * 128 + ((ac ^ (arow & 7)) << 4)));
                        }
                        uint32_t b0, b1r, b2, b3;
                        int brow = wn * 8 + (lane & 7);
                        int bc   = kk2 * 4 + ((lane >> 3) & 3);
                        LDMATRIX_X4(b0, b1r, b2, b3,
                                    wB + (uint32_t)(brow * 128 + ((bc ^ (brow & 7)) << 4)));
                        MMA16816(acc[0], aR[0][0], aR[0][1], aR[0][2], aR[0][3], b0, b1r);
                        MMA16816(acc[0], aR[1][0], aR[1][1], aR[1][2], aR[1][3], b2, b3);
                    }
                }
                __syncthreads();
            }

            // ---------------- epilogue ----------------
            const int g = lane >> 2, tg = lane & 3;
            if (isL0) {
                const float* A0t = g_A0 + (size_t)t * BATCH * HID;
                __half* l0n  = g_L0A + (size_t)(t + 1) * BATCH * 1536;
                __half* l1h0 = g_L1A + (size_t)t * BATCH * 3072;
#pragma unroll
                for (int j = 0; j < 2; j++) {
                    int col = nbase + wn * 16 + j * 8 + tg * 2;
#pragma unroll
                    for (int h = 0; h < 2; h++) {
                        int brow = mb + wm * 16 + g + h * 8;
                        float2 a0v = *(const float2*)&A0t[(size_t)brow * 512 + col];
                        float x0 = tanhf(acc[j][h * 2 + 0] + a0v.x);
                        float x1 = tanhf(acc[j][h * 2 + 1] + a0v.y);
                        __half h0 = __float2half_rn(x0), h1 = __float2half_rn(x1);
                        __half l0 = __float2half_rn(x0 - __half2float(h0));
                        __half l1 = __float2half_rn(x1 - __half2float(h1));
                        __half2 hi2 = __halves2half2(h0, h1);
                        __half2 lo2 = __halves2half2(l0, l1);
                        size_t r0 = (size_t)brow * 1536;
                        *(__half2*)&l0n[r0 + col]        = hi2;
                        *(__half2*)&l0n[r0 + 512 + col]  = hi2;
                        *(__half2*)&l0n[r0 + 1024 + col] = lo2;
                        size_t r1 = (size_t)brow * 3072;
                        *(__half2*)&l1h0[r1 + col]        = hi2;
                        *(__half2*)&l1h0[r1 + 512 + col]  = hi2;
                        *(__half2*)&l1h0[r1 + 1024 + col] = lo2;
                        if (t == S_LEN - 1)
                            *(float2*)&g_H0[((size_t)t * BATCH + brow) * 512 + col] =
                                make_float2(x0, x1);
                    }
                }
            } else {
                __half* l1n = g_L1A + (size_t)(t + 1) * BATCH * 3072 + 1536;
                int col = nbase + wn * 8 + tg * 2;
                float2 bv = *(const float2*)&b1[col];
#pragma unroll
                for (int h = 0; h < 2; h++) {
                    int brow = mb + wm * 16 + g + h * 8;
                    float x0 = tanhf(acc[0][h * 2 + 0] + bv.x);
                    float x1 = tanhf(acc[0][h * 2 + 1] + bv.y);
                    __half h0 = __float2half_rn(x0), h1 = __float2half_rn(x1);
                    __half l0 = __float2half_rn(x0 - __half2float(h0));
                    __half l1 = __float2half_rn(x1 - __half2float(h1));
                    __half2 hi2 = __halves2half2(h0, h1);
                    __half2 lo2 = __halves2half2(l0, l1);
                    size_t r1 = (size_t)brow * 3072;
                    *(__half2*)&l1n[r1 + col]        = hi2;
                    *(__half2*)&l1n[r1 + 512 + col]  = hi2;
                    *(__half2*)&l1n[r1 + 1024 + col] = lo2;
                    *(__half2*)&g_H1H[((size_t)t * BATCH + brow) * 512 + col] = hi2;
                    if (t == S_LEN - 1)
                        *(float2*)&g_H1[((size_t)t * BATCH + brow) * 512 + col] =
                            make_float2(x0, x1);
                }
            }
        }

        // grid barrier (proven)
        if (p < S_LEN) {
            __syncthreads();
            __threadfence();
            if (tid == 0) {
                unsigned target = (unsigned)REC_CTAS * (unsigned)(p + 1);
                atomicAdd(&g_arrive, 1u);
                while (atomicAdd(&g_arrive, 0u) < target) { }
                __threadfence();
            }
            __syncthreads();
        }
    }
}

// ---------------------------------------------------------------------------
__global__ void copy_hidden_kernel(float* __restrict__ dst)
{
    const int BH = BATCH * HID;
    int i = blockIdx.x * blockDim.x + threadIdx.x;
    if (i < BH)           dst[i] = g_H0[(size_t)(S_LEN - 1) * BH + i];
    else if (i < 2 * BH)  dst[i] = g_H1[(size_t)(S_LEN - 1) * BH + (i - BH)];
}

// ---------------------------------------------------------------------------
extern "C" void kernel_launch(void* const* d_in, const int* in_sizes, int n_in,
                              void* d_out, int out_size)
{
    const int*   inputs = (const int*)  d_in[0];
    const float* hidden = (const float*)d_in[1];
    const float* emb    = (const float*)d_in[2];
    const float* W0     = (const float*)d_in[3];
    const float* b0     = (const float*)d_in[4];
    const float* W1     = (const float*)d_in[5];
    const float* b1     = (const float*)d_in[6];
    const float* Wout   = (const float*)d_in[7];
    const float* bout   = (const float*)d_in[8];
    float* out = (float*)d_out;

    cudaFuncSetAttribute(gemm_fp16_mma, cudaFuncAttributeMaxDynamicSharedMemorySize,
                         GEMM_SMEM);
    cudaFuncSetAttribute(rnn_rec_tc, cudaFuncAttributeMaxDynamicSharedMemorySize,
                         REC_SMEM);

    __half *embS, *w0xS, *woutH, *h1H, *w0hS, *w1S, *l0a, *l1a;
    float *a0;
    cudaGetSymbolAddress((void**)&embS,  g_embS);
    cudaGetSymbolAddress((void**)&w0xS,  g_W0xS);
    cudaGetSymbolAddress((void**)&woutH, g_WoutH);
    cudaGetSymbolAddress((void**)&h1H,   g_H1H);
    cudaGetSymbolAddress((void**)&w0hS,  g_W0hS);
    cudaGetSymbolAddress((void**)&w1S,   g_W1S);
    cudaGetSymbolAddress((void**)&l0a,   g_L0A);
    cudaGetSymbolAddress((void**)&l1a,   g_L1A);
    cudaGetSymbolAddress((void**)&a0,    g_A0);

    const int BH = BATCH * HID;

    // 1) grid-barrier reset
    reset_barrier_kernel<<<1, 1>>>();

    // 2) operand conversions / splits
    split_half_ld<<<(VOCAB * 512 + 255) / 256, 256>>>(emb, 512, VOCAB, embS, 1536, 0, VOCAB, 0);
    split_half_ld<<<(HID * 512 + 255) / 256, 256>>>(W0,       1024, HID, w0xS, 1536, 0,    HID, 1);
    split_half_ld<<<(HID * 512 + 255) / 256, 256>>>(W0 + 512, 1024, HID, w0hS, 1536, 0,    HID, 1);
    split_half_ld<<<(HID * 512 + 255) / 256, 256>>>(W1,       1024, HID, w1S,  3072, 0,    HID, 1);
    split_half_ld<<<(HID * 512 + 255) / 256, 256>>>(W1 + 512, 1024, HID, w1S,  3072, 1536, HID, 1);
    to_half_kernel<<<(NPAD * 512 + 255) / 256, 256>>>(Wout, 512, VOCAB, woutH, NPAD);
    // initial hidden splits
    split_half_ld<<<(BATCH * 512 + 255) / 256, 256>>>(hidden,      512, BATCH, l0a, 1536, 0,    BATCH, 0);
    split_half_ld<<<(BATCH * 512 + 255) / 256, 256>>>(hidden + BH, 512, BATCH, l1a, 3072, 1536, BATCH, 0);

    // 3) input projection (HMMA, split K=1536): g_A0 = emb[tok] @ W0x^T + b0
    {
        dim3 grid(HID / 128, (S_LEN * BATCH) / 128);
        gemm_fp16_mma<<<grid, 256, GEMM_SMEM>>>(embS, inputs, w0xS, b0, a0, HID, HID, 1536);
    }

    // 4) recurrence: persistent tensor-core kernel (fp16-split, W smem-resident)
    rnn_rec_tc<<<REC_CTAS, 256, REC_SMEM>>>(b1);

    // 5) logits = H1 @ Wout^T + bout (HMMA, K=512; H1H written by recurrence)
    {
        dim3 grid(NPAD / 128, (S_LEN * BATCH) / 128);
        gemm_fp16_mma<<<grid, 256, GEMM_SMEM>>>(h1H, nullptr, woutH, bout, out, VOCAB,
                                                VOCAB, 512);
    }

    // 6) final hidden tail if the output buffer carries it
    long long need = (long long)S_LEN * BATCH * VOCAB + 2LL * BATCH * HID;
    if ((long long)out_size >= need) {
        float* tail = out + (size_t)S_LEN * BATCH * VOCAB;
        copy_hidden_kernel<<<(2 * BATCH * HID) / 256, 256>>>(tail);
    }
}

// round 8
// speedup vs baseline: 3.8146x; 1.2368x over previous
#include <cuda_runtime.h>
#include <cuda_fp16.h>
#include <math.h>
#include <stdint.h>

#define S_LEN 128
#define BATCH 128
#define VOCAB 10000
#define NPAD  10240
#define EMB   512
#define HID   512

// ---------------- scratch (device globals: allocation-free) ----------------
__device__ float g_A0[S_LEN * BATCH * HID];   // emb[tok] @ W0x^T + b0, all steps
__device__ float g_H0[S_LEN * BATCH * HID];   // layer-0 hidden (only t=127 written)
__device__ float g_H1[S_LEN * BATCH * HID];   // layer-1 hidden (only t=127 written)
__device__ unsigned g_arrive;                 // grid barrier counter

// fp16 operands (embed + logits GEMMs, 3-term layout, unchanged)
__device__ __half g_embS [VOCAB * 1536];           // A-side split: [hi|hi|lo]
__device__ __half g_W0xS [HID * 1536];             // B-side split: [hi|lo|hi]
__device__ __half g_WoutH[NPAD * 512];             // B-side plain fp16, zero-padded
__device__ __half g_H1H  [S_LEN * BATCH * 512];    // A-side plain fp16 (logits input)

// recurrence operands, DEDUP layout [hi|lo]
__device__ __half g_W0hS[HID * 1024];              // W0[:,512:1024] [hi|lo]
__device__ __half g_W1S [HID * 2048];              // [W1x hi|lo | W1h hi|lo]
__device__ __half g_L0A [(S_LEN + 1) * BATCH * 1024]; // h0[t-1]: [hi|lo]
__device__ __half g_L1A [(S_LEN + 1) * BATCH * 2048]; // [h0 hi|lo | h1 hi|lo]

// =================== helpers ========================
__device__ __forceinline__ uint32_t smem_u32(const void* p) {
    uint32_t a;
    asm("{ .reg .u64 t; cvta.to.shared.u64 t, %1; cvt.u32.u64 %0, t; }" : "=r"(a) : "l"(p));
    return a;
}

#define CP_ASYNC16(dst, src) \
    asm volatile("cp.async.cg.shared.global [%0], [%1], 16;" :: "r"(dst), "l"(src) : "memory")
#define CP_COMMIT() asm volatile("cp.async.commit_group;" ::: "memory")
#define CP_WAIT1()  asm volatile("cp.async.wait_group 1;" ::: "memory")
#define CP_WAIT3()  asm volatile("cp.async.wait_group 3;" ::: "memory")

#define LDMATRIX_X4(r0, r1, r2, r3, addr) \
    asm volatile("ldmatrix.sync.aligned.m8n8.x4.shared.b16 {%0,%1,%2,%3}, [%4];" \
                 : "=r"(r0), "=r"(r1), "=r"(r2), "=r"(r3) : "r"(addr))

#define MMA16816(c, a0, a1, a2, a3, b0, b1) \
    asm volatile("mma.sync.aligned.m16n8k16.row.col.f32.f16.f16.f32 " \
        "{%0,%1,%2,%3},{%4,%5,%6,%7},{%8,%9},{%10,%11,%12,%13};" \
        : "=f"((c)[0]), "=f"((c)[1]), "=f"((c)[2]), "=f"((c)[3]) \
        : "r"(a0), "r"(a1), "r"(a2), "r"(a3), "r"(b0), "r"(b1), \
          "f"((c)[0]), "f"((c)[1]), "f"((c)[2]), "f"((c)[3]))

// ======================= conversions ===========================
__global__ void to_half_kernel(const float* __restrict__ src, int src_ld, int src_rows,
                               __half* __restrict__ dst, int dst_rows)
{
    int i = blockIdx.x * blockDim.x + threadIdx.x;
    if (i >= dst_rows * 512) return;
    int r = i >> 9, c = i & 511;
    float x = (r < src_rows) ? src[(size_t)r * src_ld + c] : 0.0f;
    dst[i] = __float2half_rn(x);
}

// split. mode 0: [hi|hi|lo]  mode 1: [hi|lo|hi]  mode 2: [hi|lo] (dedup)
__global__ void split_half_ld(const float* __restrict__ src, int src_ld, int src_rows,
                              __half* __restrict__ dst, long long dst_ld, long long dst_off,
                              int dst_rows, int mode)
{
    int i = blockIdx.x * blockDim.x + threadIdx.x;
    if (i >= dst_rows * 512) return;
    int r = i >> 9, c = i & 511;
    float x = (r < src_rows) ? src[(size_t)r * src_ld + c] : 0.0f;
    __half hi = __float2half_rn(x);
    __half lo = __float2half_rn(x - __half2float(hi));
    size_t base = (size_t)r * dst_ld + dst_off;
    dst[base + c] = hi;
    if (mode == 1)      { dst[base + 512 + c] = lo; dst[base + 1024 + c] = hi; }
    else if (mode == 0) { dst[base + 512 + c] = hi; dst[base + 1024 + c] = lo; }
    else                { dst[base + 512 + c] = lo; }
}

// ============= fp16 mma.sync GEMM: C = A @ B^T + bias (fp32 out) ===========
#define GEMM_SMEM (4 * 128 * 128)   // 64KB

__global__ void __launch_bounds__(256) gemm_fp16_mma(
    const __half* __restrict__ A,
    const int* __restrict__ gather,
    const __half* __restrict__ B,
    const float* __restrict__ bias,
    float* __restrict__ C, int ldc, int Nreal, int K)
{
    extern __shared__ __align__(1024) char smem[];
    const uint32_t sbase = smem_u32(smem);
    const uint32_t offA[2] = { 0u, 16384u };
    const uint32_t offB[2] = { 32768u, 49152u };

    const int tid  = threadIdx.x;
    const int lane = tid & 31;
    const int w    = tid >> 5;
    const int wm   = w >> 2;
    const int wn   = w & 3;
    const int m0   = blockIdx.y * 128;
    const int n0   = blockIdx.x * 128;

    const __half* asrc[4]; uint32_t adst[4];
    const __half* bsrc[4]; uint32_t bdst[4];
#pragma unroll
    for (int j = 0; j < 4; j++) {
        int id = tid + j * 256;
        int r = id >> 3, c = id & 7;
        int row = m0 + r;
        if (gather) row = gather[row];
        asrc[j] = A + (size_t)row * K + c * 8;
        adst[j] = (uint32_t)(r * 128 + ((c ^ (r & 7)) << 4));
        bsrc[j] = B + (size_t)(n0 + r) * K + c * 8;
        bdst[j] = adst[j];
    }

    float acc[4][4][4];
#pragma unroll
    for (int i = 0; i < 4; i++)
#pragma unroll
        for (int j = 0; j < 4; j++)
#pragma unroll
            for (int k = 0; k < 4; k++) acc[i][j][k] = 0.0f;

#pragma unroll
    for (int j = 0; j < 4; j++) {
        CP_ASYNC16(sbase + offA[0] + adst[j], asrc[j]);
        CP_ASYNC16(sbase + offB[0] + bdst[j], bsrc[j]);
    }
    CP_COMMIT();

    const int nst = K >> 6;
#pragma unroll 1
    for (int s = 0; s < nst; s++) {
        if (s + 1 < nst) {
            const int nb = (s + 1) & 1;
            const int ke = (s + 1) * 64;
#pragma unroll
            for (int j = 0; j < 4; j++) {
                CP_ASYNC16(sbase + offA[nb] + adst[j], asrc[j] + ke);
                CP_ASYNC16(sbase + offB[nb] + bdst[j], bsrc[j] + ke);
            }
        }
        CP_COMMIT();
        CP_WAIT1();
        __syncthreads();

        const uint32_t aBase = sbase + offA[s & 1];
        const uint32_t bBase = sbase + offB[s & 1];

#pragma unroll
        for (int kk = 0; kk < 4; kk++) {
            uint32_t aR[4][4], bR[4][2];
#pragma unroll
            for (int t = 0; t < 4; t++) {
                int row = wm * 64 + t * 16 + (lane & 15);
                int c   = kk * 2 + (lane >> 4);
                uint32_t ad = aBase + (uint32_t)(row * 128 + ((c ^ (row & 7)) << 4));
                LDMATRIX_X4(aR[t][0], aR[t][1], aR[t][2], aR[t][3], ad);
            }
#pragma unroll
            for (int p = 0; p < 2; p++) {
                int nrow = wn * 32 + p * 16 + (lane & 7) + ((lane >> 4) << 3);
                int c    = kk * 2 + ((lane >> 3) & 1);
                uint32_t bd = bBase + (uint32_t)(nrow * 128 + ((c ^ (nrow & 7)) << 4));
                uint32_t r0, r1, r2, r3;
                LDMATRIX_X4(r0, r1, r2, r3, bd);
                bR[p * 2 + 0][0] = r0; bR[p * 2 + 0][1] = r1;
                bR[p * 2 + 1][0] = r2; bR[p * 2 + 1][1] = r3;
            }
#pragma unroll
            for (int i = 0; i < 4; i++)
#pragma unroll
                for (int j = 0; j < 4; j++)
                    MMA16816(acc[i][j], aR[i][0], aR[i][1], aR[i][2], aR[i][3],
                             bR[j][0], bR[j][1]);
        }
        __syncthreads();
    }

    const int g  = lane >> 2;
    const int tg = lane & 3;
#pragma unroll
    for (int j = 0; j < 4; j++) {
        int col = n0 + wn * 32 + j * 8 + tg * 2;
        if (col >= Nreal) continue;
        float2 bv = *(const float2*)&bias[col];
#pragma unroll
        for (int i = 0; i < 4; i++) {
            int r0 = m0 + wm * 64 + i * 16 + g;
            float2 v0 = make_float2(acc[i][j][0] + bv.x, acc[i][j][1] + bv.y);
            float2 v1 = make_float2(acc[i][j][2] + bv.x, acc[i][j][3] + bv.y);
            *(float2*)&C[(size_t)r0 * ldc + col]       = v0;
            *(float2*)&C[(size_t)(r0 + 8) * ldc + col] = v1;
        }
    }
}

// ===================== tensor-core recurrent kernel (v2) ===================
// Dedup [hi|lo] operands; hi A-frags reused for W-hi AND W-lo targets.
// 96 CTAs. L0 (0..31): tile 64x32, A K=1024 (8 stages). L1 (32..95): tile
// 64x16, A K=2048 (16 stages). W resident 64KB; 5x16KB A stage ring, one
// __syncthreads per stage.
#define REC_CTAS 96
#define REC_AOFF 65536
#define REC_SMEM (65536 + 5 * 16384)   // 147456

__global__ void reset_barrier_kernel() { g_arrive = 0u; }

__global__ void __launch_bounds__(256) rnn_rec_tc(const float* __restrict__ b1)
{
    extern __shared__ __align__(1024) char smem[];
    const uint32_t sbase = smem_u32(smem);
    const int bid  = blockIdx.x;
    const int tid  = threadIdx.x;
    const int lane = tid & 31;
    const int w    = tid >> 5;
    const int wm   = w >> 1;        // 0..3 (m16 slab within 64 rows)
    const int wn   = w & 1;
    const bool isL0 = (bid < 32);

    int nbase, mb, AK, NSTG, WBLK, wrows;
    const __half* Wsrc;
    const __half* Abase0;
    if (isL0) {
        nbase = (bid >> 1) * 32; mb = (bid & 1) * 64;
        AK = 1024; NSTG = 8; WBLK = 4096; wrows = 32;
        Wsrc = g_W0hS; Abase0 = g_L0A;
    } else {
        int q = bid - 32;
        nbase = (q >> 1) * 16; mb = (q & 1) * 64;
        AK = 2048; NSTG = 16; WBLK = 2048; wrows = 16;
        Wsrc = g_W1S; Abase0 = g_L1A;
    }
    const int NB = AK >> 6;                 // 64-half W blocks (16 / 32)

    // ---- W slice resident in smem: NB blocks of [wrows x 128B], swizzled ----
    {
        const int per = wrows * 8;
        const int chunks = NB * per;        // 4096 both layers
        for (int id = tid; id < chunks; id += 256) {
            int u = id / per, rem = id % per;
            int r = rem >> 3, c8 = rem & 7;
            uint32_t off = (uint32_t)(u * WBLK + r * 128 + ((c8 ^ (r & 7)) << 4));
            *(uint4*)(smem + off) =
                *(const uint4*)(Wsrc + (size_t)(nbase + r) * AK + u * 64 + c8 * 8);
        }
    }
    __syncthreads();

    // A load slots: 4 x 16B chunks per thread per 16KB stage (2 x 8KB blocks)
    int arow4[4], acol4[4]; uint32_t adst4[4];
#pragma unroll
    for (int j = 0; j < 4; j++) {
        int id = tid + j * 256;             // 0..1023
        int blk = id >> 9, rem = id & 511;
        int r = rem >> 3, c8 = rem & 7;
        arow4[j] = r;
        acol4[j] = blk * 64 + c8 * 8;
        adst4[j] = (uint32_t)(blk * 8192 + r * 128 + ((c8 ^ (r & 7)) << 4));
    }

#pragma unroll 1
    for (int p = 0; p <= S_LEN; p++) {
        const bool active = isL0 ? (p < S_LEN) : (p >= 1);
        if (active) {
            const int t = isL0 ? p : (p - 1);
            const __half* Ab = Abase0 + (size_t)t * BATCH * AK;
            const __half* aptr4[4];
#pragma unroll
            for (int j = 0; j < 4; j++)
                aptr4[j] = Ab + (size_t)(mb + arow4[j]) * AK + acol4[j];

            float acc[2][4];
#pragma unroll
            for (int i = 0; i < 2; i++)
#pragma unroll
                for (int k = 0; k < 4; k++) acc[i][k] = 0.0f;

#define REC_ISSUE(ss, bi) do {                                             \
    uint32_t buf = sbase + REC_AOFF + (uint32_t)(bi) * 16384u;             \
    CP_ASYNC16(buf + adst4[0], aptr4[0] + (ss) * 128);                     \
    CP_ASYNC16(buf + adst4[1], aptr4[1] + (ss) * 128);                     \
    CP_ASYNC16(buf + adst4[2], aptr4[2] + (ss) * 128);                     \
    CP_ASYNC16(buf + adst4[3], aptr4[3] + (ss) * 128);                     \
} while (0)

            REC_ISSUE(0, 0); CP_COMMIT();
            REC_ISSUE(1, 1); CP_COMMIT();
            REC_ISSUE(2, 2); CP_COMMIT();

#pragma unroll 1
            for (int s = 0; s < NSTG; s++) {
                if (s + 3 < NSTG) REC_ISSUE(s + 3, (s + 3) % 5);
                CP_COMMIT();
                CP_WAIT3();
                __syncthreads();        // single sync: depth-5 ring guards reuse

                const uint32_t aB = sbase + REC_AOFF + (uint32_t)(s % 5) * 16384u;

#pragma unroll
                for (int b = 0; b < 2; b++) {           // two 64-half sub-blocks
                    const int u = 2 * s + b;            // A-SUB index over AK/64
                    const bool hiseg = ((u >> 3) & 1) == 0;
                    const int ut0 = hiseg ? u : (u - 8);

                    // A fragments for this SUB (4 k-steps), reused per W target
                    uint32_t aR[4][4];
#pragma unroll
                    for (int kk = 0; kk < 4; kk++) {
                        int arow = wm * 16 + (lane & 15);
                        int ac   = kk * 2 + (lane >> 4);
                        LDMATRIX_X4(aR[kk][0], aR[kk][1], aR[kk][2], aR[kk][3],
                                    aB + (uint32_t)(b * 8192 + arow * 128 +
                                                    ((ac ^ (arow & 7)) << 4)));
                    }
                    const int ntgt = hiseg ? 2 : 1;
#pragma unroll
                    for (int tg_ = 0; tg_ < 2; tg_++) {
                        if (tg_ >= ntgt) break;
                        const int ut = tg_ == 0 ? ut0 : (u + 8);
                        const uint32_t wB = sbase + (uint32_t)(ut * WBLK);
                        if (isL0) {
#pragma unroll
                            for (int kk = 0; kk < 4; kk++) {
                                int brow = wn * 16 + (lane & 7) + ((lane >> 4) << 3);
                                int bc   = kk * 2 + ((lane >> 3) & 1);
                                uint32_t b0, b1r, b2, b3;
                                LDMATRIX_X4(b0, b1r, b2, b3,
                                            wB + (uint32_t)(brow * 128 +
                                                            ((bc ^ (brow & 7)) << 4)));
                                MMA16816(acc[0], aR[kk][0], aR[kk][1], aR[kk][2], aR[kk][3], b0, b1r);
                                MMA16816(acc[1], aR[kk][0], aR[kk][1], aR[kk][2], aR[kk][3], b2, b3);
                            }
                        } else {
#pragma unroll
                            for (int kk2 = 0; kk2 < 2; kk2++) {
                                int brow = wn * 8 + (lane & 7);
                                int bc   = kk2 * 4 + ((lane >> 3) & 3);
                                uint32_t b0, b1r, b2, b3;
                                LDMATRIX_X4(b0, b1r, b2, b3,
                                            wB + (uint32_t)(brow * 128 +
                                                            ((bc ^ (brow & 7)) << 4)));
                                MMA16816(acc[0], aR[kk2*2][0], aR[kk2*2][1], aR[kk2*2][2], aR[kk2*2][3], b0, b1r);
                                MMA16816(acc[0], aR[kk2*2+1][0], aR[kk2*2+1][1], aR[kk2*2+1][2], aR[kk2*2+1][3], b2, b3);
                            }
                        }
                    }
                }
            }

            // ---------------- epilogue (dedup [hi|lo] stores) ----------------
            const int g = lane >> 2, tg = lane & 3;
            if (isL0) {
                const float* A0t = g_A0 + (size_t)t * BATCH * HID;
                __half* l0n  = g_L0A + (size_t)(t + 1) * BATCH * 1024;
                __half* l1h0 = g_L1A + (size_t)t * BATCH * 2048;
#pragma unroll
                for (int j = 0; j < 2; j++) {
                    int col = nbase + wn * 16 + j * 8 + tg * 2;
#pragma unroll
                    for (int h = 0; h < 2; h++) {
                        int brow = mb + wm * 16 + g + h * 8;
                        float2 a0v = *(const float2*)&A0t[(size_t)brow * 512 + col];
                        float x0 = tanhf(acc[j][h * 2 + 0] + a0v.x);
                        float x1 = tanhf(acc[j][h * 2 + 1] + a0v.y);
                        __half h0 = __float2half_rn(x0), h1 = __float2half_rn(x1);
                        __half l0 = __float2half_rn(x0 - __half2float(h0));
                        __half l1 = __float2half_rn(x1 - __half2float(h1));
                        __half2 hi2 = __halves2half2(h0, h1);
                        __half2 lo2 = __halves2half2(l0, l1);
                        size_t r0 = (size_t)brow * 1024;
                        *(__half2*)&l0n[r0 + col]       = hi2;
                        *(__half2*)&l0n[r0 + 512 + col] = lo2;
                        size_t r1 = (size_t)brow * 2048;
                        *(__half2*)&l1h0[r1 + col]       = hi2;
                        *(__half2*)&l1h0[r1 + 512 + col] = lo2;
                        if (t == S_LEN - 1)
                            *(float2*)&g_H0[((size_t)t * BATCH + brow) * 512 + col] =
                                make_float2(x0, x1);
                    }
                }
            } else {
                __half* l1n = g_L1A + (size_t)(t + 1) * BATCH * 2048;
                int col = nbase + wn * 8 + tg * 2;
                float2 bv = *(const float2*)&b1[col];
#pragma unroll
                for (int h = 0; h < 2; h++) {
                    int brow = mb + wm * 16 + g + h * 8;
                    float x0 = tanhf(acc[0][h * 2 + 0] + bv.x);
                    float x1 = tanhf(acc[0][h * 2 + 1] + bv.y);
                    __half h0 = __float2half_rn(x0), h1 = __float2half_rn(x1);
                    __half l0 = __float2half_rn(x0 - __half2float(h0));
                    __half l1 = __float2half_rn(x1 - __half2float(h1));
                    __half2 hi2 = __halves2half2(h0, h1);
                    __half2 lo2 = __halves2half2(l0, l1);
                    size_t r1 = (size_t)brow * 2048;
                    *(__half2*)&l1n[r1 + 1024 + col] = hi2;
                    *(__half2*)&l1n[r1 + 1536 + col] = lo2;
                    *(__half2*)&g_H1H[((size_t)t * BATCH + brow) * 512 + col] = hi2;
                    if (t == S_LEN - 1)
                        *(float2*)&g_H1[((size_t)t * BATCH + brow) * 512 + col] =
                            make_float2(x0, x1);
                }
            }
        }

        // grid barrier: release-arrive + acquire-load poll (no atomic spin)
        if (p < S_LEN) {
            __syncthreads();
            __threadfence();
            if (tid == 0) {
                atomicAdd(&g_arrive, 1u);
                unsigned target = (unsigned)REC_CTAS * (unsigned)(p + 1);
                unsigned v;
                do {
                    asm volatile("ld.acquire.gpu.global.u32 %0, [%1];"
                                 : "=r"(v) : "l"(&g_arrive));
                } while (v < target);
            }
            __syncthreads();
        }
    }
}

// ---------------------------------------------------------------------------
__global__ void copy_hidden_kernel(float* __restrict__ dst)
{
    const int BH = BATCH * HID;
    int i = blockIdx.x * blockDim.x + threadIdx.x;
    if (i < BH)           dst[i] = g_H0[(size_t)(S_LEN - 1) * BH + i];
    else if (i < 2 * BH)  dst[i] = g_H1[(size_t)(S_LEN - 1) * BH + (i - BH)];
}

// ---------------------------------------------------------------------------
extern "C" void kernel_launch(void* const* d_in, const int* in_sizes, int n_in,
                              void* d_out, int out_size)
{
    const int*   inputs = (const int*)  d_in[0];
    const float* hidden = (const float*)d_in[1];
    const float* emb    = (const float*)d_in[2];
    const float* W0     = (const float*)d_in[3];
    const float* b0     = (const float*)d_in[4];
    const float* W1     = (const float*)d_in[5];
    const float* b1     = (const float*)d_in[6];
    const float* Wout   = (const float*)d_in[7];
    const float* bout   = (const float*)d_in[8];
    float* out = (float*)d_out;

    cudaFuncSetAttribute(gemm_fp16_mma, cudaFuncAttributeMaxDynamicSharedMemorySize,
                         GEMM_SMEM);
    cudaFuncSetAttribute(rnn_rec_tc, cudaFuncAttributeMaxDynamicSharedMemorySize,
                         REC_SMEM);

    __half *embS, *w0xS, *woutH, *h1H, *w0hS, *w1S, *l0a, *l1a;
    float *a0;
    cudaGetSymbolAddress((void**)&embS,  g_embS);
    cudaGetSymbolAddress((void**)&w0xS,  g_W0xS);
    cudaGetSymbolAddress((void**)&woutH, g_WoutH);
    cudaGetSymbolAddress((void**)&h1H,   g_H1H);
    cudaGetSymbolAddress((void**)&w0hS,  g_W0hS);
    cudaGetSymbolAddress((void**)&w1S,   g_W1S);
    cudaGetSymbolAddress((void**)&l0a,   g_L0A);
    cudaGetSymbolAddress((void**)&l1a,   g_L1A);
    cudaGetSymbolAddress((void**)&a0,    g_A0);

    const int BH = BATCH * HID;

    // 1) grid-barrier reset
    reset_barrier_kernel<<<1, 1>>>();

    // 2) operand conversions / splits
    split_half_ld<<<(VOCAB * 512 + 255) / 256, 256>>>(emb, 512, VOCAB, embS, 1536, 0, VOCAB, 0);
    split_half_ld<<<(HID * 512 + 255) / 256, 256>>>(W0,       1024, HID, w0xS, 1536, 0,    HID, 1);
    split_half_ld<<<(HID * 512 + 255) / 256, 256>>>(W0 + 512, 1024, HID, w0hS, 1024, 0,    HID, 2);
    split_half_ld<<<(HID * 512 + 255) / 256, 256>>>(W1,       1024, HID, w1S,  2048, 0,    HID, 2);
    split_half_ld<<<(HID * 512 + 255) / 256, 256>>>(W1 + 512, 1024, HID, w1S,  2048, 1024, HID, 2);
    to_half_kernel<<<(NPAD * 512 + 255) / 256, 256>>>(Wout, 512, VOCAB, woutH, NPAD);
    // initial hidden splits (dedup layout)
    split_half_ld<<<(BATCH * 512 + 255) / 256, 256>>>(hidden,      512, BATCH, l0a, 1024, 0,    BATCH, 2);
    split_half_ld<<<(BATCH * 512 + 255) / 256, 256>>>(hidden + BH, 512, BATCH, l1a, 2048, 1024, BATCH, 2);

    // 3) input projection (HMMA, 3-term K=1536): g_A0 = emb[tok] @ W0x^T + b0
    {
        dim3 grid(HID / 128, (S_LEN * BATCH) / 128);
        gemm_fp16_mma<<<grid, 256, GEMM_SMEM>>>(embS, inputs, w0xS, b0, a0, HID, HID, 1536);
    }

    // 4) recurrence: persistent tensor-core kernel v2 (dedup, 1-sync stages)
    rnn_rec_tc<<<REC_CTAS, 256, REC_SMEM>>>(b1);

    // 5) logits = H1 @ Wout^T + bout (HMMA, K=512; H1H written by recurrence)
    {
        dim3 grid(NPAD / 128, (S_LEN * BATCH) / 128);
        gemm_fp16_mma<<<grid, 256, GEMM_SMEM>>>(h1H, nullptr, woutH, bout, out, VOCAB,
                                                VOCAB, 512);
    }

    // 6) final hidden tail if the output buffer carries it
    long long need = (long long)S_LEN * BATCH * VOCAB + 2LL * BATCH * HID;
    if ((long long)out_size >= need) {
        float* tail = out + (size_t)S_LEN * BATCH * VOCAB;
        copy_hidden_kernel<<<(2 * BATCH * HID) / 256, 256>>>(tail);
    }
}

// round 9
// speedup vs baseline: 4.2812x; 1.1223x over previous
#include <cuda_runtime.h>
#include <cuda_fp16.h>
#include <math.h>
#include <stdint.h>

#define S_LEN 128
#define BATCH 128
#define VOCAB 10000
#define NPAD  10240
#define EMB   512
#define HID   512

// ---------------- scratch (device globals: allocation-free) ----------------
__device__ float g_A0[S_LEN * BATCH * HID];
__device__ float g_H0[S_LEN * BATCH * HID];
__device__ float g_H1[S_LEN * BATCH * HID];
__device__ unsigned g_arrive;

// fp16 operands (embed + logits GEMMs)
__device__ __half g_embS [VOCAB * 1536];           // [hi|hi|lo]
__device__ __half g_W0xS [HID * 1536];             // [hi|lo|hi]
__device__ __half g_WoutH[NPAD * 512];
__device__ __half g_H1H  [S_LEN * BATCH * 512];

// recurrence operands, dedup [hi|lo]
__device__ __half g_W0hS[HID * 1024];
__device__ __half g_W1S [HID * 2048];              // [W1x hi|lo | W1h hi|lo]
__device__ __half g_L0A [(S_LEN + 1) * BATCH * 1024];
__device__ __half g_L1A [(S_LEN + 1) * BATCH * 2048];

// =================== helpers ========================
__device__ __forceinline__ uint32_t smem_u32(const void* p) {
    uint32_t a;
    asm("{ .reg .u64 t; cvta.to.shared.u64 t, %1; cvt.u32.u64 %0, t; }" : "=r"(a) : "l"(p));
    return a;
}

#define CP_ASYNC16(dst, src) \
    asm volatile("cp.async.cg.shared.global [%0], [%1], 16;" :: "r"(dst), "l"(src) : "memory")
#define CP_COMMIT() asm volatile("cp.async.commit_group;" ::: "memory")
#define CP_WAIT1()  asm volatile("cp.async.wait_group 1;" ::: "memory")
#define CP_WAIT3()  asm volatile("cp.async.wait_group 3;" ::: "memory")

#define LDMATRIX_X4(r0, r1, r2, r3, addr) \
    asm volatile("ldmatrix.sync.aligned.m8n8.x4.shared.b16 {%0,%1,%2,%3}, [%4];" \
                 : "=r"(r0), "=r"(r1), "=r"(r2), "=r"(r3) : "r"(addr))

#define MMA16816(c, a0, a1, a2, a3, b0, b1) \
    asm volatile("mma.sync.aligned.m16n8k16.row.col.f32.f16.f16.f32 " \
        "{%0,%1,%2,%3},{%4,%5,%6,%7},{%8,%9},{%10,%11,%12,%13};" \
        : "=f"((c)[0]), "=f"((c)[1]), "=f"((c)[2]), "=f"((c)[3]) \
        : "r"(a0), "r"(a1), "r"(a2), "r"(a3), "r"(b0), "r"(b1), \
          "f"((c)[0]), "f"((c)[1]), "f"((c)[2]), "f"((c)[3]))

// ======================= conversions ===========================
__global__ void to_half_kernel(const float* __restrict__ src, int src_ld, int src_rows,
                               __half* __restrict__ dst, int dst_rows)
{
    int i = blockIdx.x * blockDim.x + threadIdx.x;
    if (i >= dst_rows * 512) return;
    int r = i >> 9, c = i & 511;
    float x = (r < src_rows) ? src[(size_t)r * src_ld + c] : 0.0f;
    dst[i] = __float2half_rn(x);
}

// mode 0: [hi|hi|lo]  mode 1: [hi|lo|hi]  mode 2: [hi|lo]
__global__ void split_half_ld(const float* __restrict__ src, int src_ld, int src_rows,
                              __half* __restrict__ dst, long long dst_ld, long long dst_off,
                              int dst_rows, int mode)
{
    int i = blockIdx.x * blockDim.x + threadIdx.x;
    if (i >= dst_rows * 512) return;
    int r = i >> 9, c = i & 511;
    float x = (r < src_rows) ? src[(size_t)r * src_ld + c] : 0.0f;
    __half hi = __float2half_rn(x);
    __half lo = __float2half_rn(x - __half2float(hi));
    size_t base = (size_t)r * dst_ld + dst_off;
    dst[base + c] = hi;
    if (mode == 1)      { dst[base + 512 + c] = lo; dst[base + 1024 + c] = hi; }
    else if (mode == 0) { dst[base + 512 + c] = hi; dst[base + 1024 + c] = lo; }
    else                { dst[base + 512 + c] = lo; }
}

// ============= fp16 mma.sync GEMM (unchanged, proven) ===========
#define GEMM_SMEM (4 * 128 * 128)

__global__ void __launch_bounds__(256) gemm_fp16_mma(
    const __half* __restrict__ A,
    const int* __restrict__ gather,
    const __half* __restrict__ B,
    const float* __restrict__ bias,
    float* __restrict__ C, int ldc, int Nreal, int K)
{
    extern __shared__ __align__(1024) char smem[];
    const uint32_t sbase = smem_u32(smem);
    const uint32_t offA[2] = { 0u, 16384u };
    const uint32_t offB[2] = { 32768u, 49152u };

    const int tid  = threadIdx.x;
    const int lane = tid & 31;
    const int w    = tid >> 5;
    const int wm   = w >> 2;
    const int wn   = w & 3;
    const int m0   = blockIdx.y * 128;
    const int n0   = blockIdx.x * 128;

    const __half* asrc[4]; uint32_t adst[4];
    const __half* bsrc[4]; uint32_t bdst[4];
#pragma unroll
    for (int j = 0; j < 4; j++) {
        int id = tid + j * 256;
        int r = id >> 3, c = id & 7;
        int row = m0 + r;
        if (gather) row = gather[row];
        asrc[j] = A + (size_t)row * K + c * 8;
        adst[j] = (uint32_t)(r * 128 + ((c ^ (r & 7)) << 4));
        bsrc[j] = B + (size_t)(n0 + r) * K + c * 8;
        bdst[j] = adst[j];
    }

    float acc[4][4][4];
#pragma unroll
    for (int i = 0; i < 4; i++)
#pragma unroll
        for (int j = 0; j < 4; j++)
#pragma unroll
            for (int k = 0; k < 4; k++) acc[i][j][k] = 0.0f;

#pragma unroll
    for (int j = 0; j < 4; j++) {
        CP_ASYNC16(sbase + offA[0] + adst[j], asrc[j]);
        CP_ASYNC16(sbase + offB[0] + bdst[j], bsrc[j]);
    }
    CP_COMMIT();

    const int nst = K >> 6;
#pragma unroll 1
    for (int s = 0; s < nst; s++) {
        if (s + 1 < nst) {
            const int nb = (s + 1) & 1;
            const int ke = (s + 1) * 64;
#pragma unroll
            for (int j = 0; j < 4; j++) {
                CP_ASYNC16(sbase + offA[nb] + adst[j], asrc[j] + ke);
                CP_ASYNC16(sbase + offB[nb] + bdst[j], bsrc[j] + ke);
            }
        }
        CP_COMMIT();
        CP_WAIT1();
        __syncthreads();

        const uint32_t aBase = sbase + offA[s & 1];
        const uint32_t bBase = sbase + offB[s & 1];

#pragma unroll
        for (int kk = 0; kk < 4; kk++) {
            uint32_t aR[4][4], bR[4][2];
#pragma unroll
            for (int t = 0; t < 4; t++) {
                int row = wm * 64 + t * 16 + (lane & 15);
                int c   = kk * 2 + (lane >> 4);
                uint32_t ad = aBase + (uint32_t)(row * 128 + ((c ^ (row & 7)) << 4));
                LDMATRIX_X4(aR[t][0], aR[t][1], aR[t][2], aR[t][3], ad);
            }
#pragma unroll
            for (int p = 0; p < 2; p++) {
                int nrow = wn * 32 + p * 16 + (lane & 7) + ((lane >> 4) << 3);
                int c    = kk * 2 + ((lane >> 3) & 1);
                uint32_t bd = bBase + (uint32_t)(nrow * 128 + ((c ^ (nrow & 7)) << 4));
                uint32_t r0, r1, r2, r3;
                LDMATRIX_X4(r0, r1, r2, r3, bd);
                bR[p * 2 + 0][0] = r0; bR[p * 2 + 0][1] = r1;
                bR[p * 2 + 1][0] = r2; bR[p * 2 + 1][1] = r3;
            }
#pragma unroll
            for (int i = 0; i < 4; i++)
#pragma unroll
                for (int j = 0; j < 4; j++)
                    MMA16816(acc[i][j], aR[i][0], aR[i][1], aR[i][2], aR[i][3],
                             bR[j][0], bR[j][1]);
        }
        __syncthreads();
    }

    const int g  = lane >> 2;
    const int tg = lane & 3;
#pragma unroll
    for (int j = 0; j < 4; j++) {
        int col = n0 + wn * 32 + j * 8 + tg * 2;
        if (col >= Nreal) continue;
        float2 bv = *(const float2*)&bias[col];
#pragma unroll
        for (int i = 0; i < 4; i++) {
            int r0 = m0 + wm * 64 + i * 16 + g;
            float2 v0 = make_float2(acc[i][j][0] + bv.x, acc[i][j][1] + bv.y);
            float2 v1 = make_float2(acc[i][j][2] + bv.x, acc[i][j][3] + bv.y);
            *(float2*)&C[(size_t)r0 * ldc + col]       = v0;
            *(float2*)&C[(size_t)(r0 + 8) * ldc + col] = v1;
        }
    }
}

// ================ tensor-core recurrent kernel v3 (warp-local) =============
// 96 CTAs. L0 (0..31): tile 128x16, K=1024, W slice 16x1024 = 32KB.
//          L1 (32..95): tile 128x8,  K=2048, W slice  8x2048 = 32KB.
// Each warp owns 16 batch rows, computes full CTA N. A loads are WARP-LOCAL:
// private 4-stage ring (4KB/stage), no block syncs inside the stage loop.
#define REC_CTAS 96
#define REC_AOFF 32768
#define REC_SMEM (32768 + 8 * 4 * 4096)   // 163840

__global__ void reset_barrier_kernel() { g_arrive = 0u; }

__global__ void __launch_bounds__(256) rnn_rec_tc(const float* __restrict__ b1)
{
    extern __shared__ __align__(1024) char smem[];
    const uint32_t sbase = smem_u32(smem);
    const int bid  = blockIdx.x;
    const int tid  = threadIdx.x;
    const int lane = tid & 31;
    const int w    = tid >> 5;          // warp 0..7 -> 16-row slab
    const bool isL0 = (bid < 32);

    int nbase, AK, NSTG, WBLK, wrows;
    const __half* Wsrc;
    const __half* Abase0;
    if (isL0) {
        nbase = bid * 16;
        AK = 1024; NSTG = 8;  WBLK = 2048; wrows = 16;
        Wsrc = g_W0hS; Abase0 = g_L0A;
    } else {
        int q = bid - 32;
        nbase = q * 8;
        AK = 2048; NSTG = 16; WBLK = 1024; wrows = 8;
        Wsrc = g_W1S; Abase0 = g_L1A;
    }
    const int NB = AK >> 6;             // W blocks (16 / 32)

    // ---- W slice resident: NB blocks of [wrows x 128B], swizzled ----
    {
        const int per = wrows * 8;
        const int chunks = NB * per;    // 2048 both layers
        for (int id = tid; id < chunks; id += 256) {
            int u = id / per, rem = id % per;
            int r = rem >> 3, c8 = rem & 7;
            uint32_t off = (uint32_t)(u * WBLK + r * 128 + ((c8 ^ (r & 7)) << 4));
            *(uint4*)(smem + off) =
                *(const uint4*)(Wsrc + (size_t)(nbase + r) * AK + u * 64 + c8 * 8);
        }
    }
    __syncthreads();

    // warp-private A ring: base + 4 stages x 4KB (stage = 16 rows x 256B)
    const uint32_t awbase = sbase + REC_AOFF + (uint32_t)w * 16384u;
    // 8 chunks per lane per stage
    int arow8[8], acol8[8]; uint32_t adst8[8];
#pragma unroll
    for (int j = 0; j < 8; j++) {
        int id = lane + j * 32;         // 0..255
        int blk = id >> 7, rem = id & 127;
        int r = rem >> 3, c8 = rem & 7;
        arow8[j] = r;
        acol8[j] = blk * 64 + c8 * 8;
        adst8[j] = (uint32_t)(blk * 2048 + r * 128 + ((c8 ^ (r & 7)) << 4));
    }

#pragma unroll 1
    for (int p = 0; p <= S_LEN; p++) {
        const bool active = isL0 ? (p < S_LEN) : (p >= 1);
        if (active) {
            const int t = isL0 ? p : (p - 1);
            const __half* Ab = Abase0 + (size_t)t * BATCH * AK + (size_t)(w * 16) * AK;
            const __half* aptr8[8];
#pragma unroll
            for (int j = 0; j < 8; j++)
                aptr8[j] = Ab + (size_t)arow8[j] * AK + acol8[j];

            float acc[2][4];
#pragma unroll
            for (int i = 0; i < 2; i++)
#pragma unroll
                for (int k = 0; k < 4; k++) acc[i][k] = 0.0f;

#define RECW_ISSUE(ss, bi) do {                                            \
    uint32_t buf = awbase + (uint32_t)(bi) * 4096u;                        \
    CP_ASYNC16(buf + adst8[0], aptr8[0] + (ss) * 128);                     \
    CP_ASYNC16(buf + adst8[1], aptr8[1] + (ss) * 128);                     \
    CP_ASYNC16(buf + adst8[2], aptr8[2] + (ss) * 128);                     \
    CP_ASYNC16(buf + adst8[3], aptr8[3] + (ss) * 128);                     \
    CP_ASYNC16(buf + adst8[4], aptr8[4] + (ss) * 128);                     \
    CP_ASYNC16(buf + adst8[5], aptr8[5] + (ss) * 128);                     \
    CP_ASYNC16(buf + adst8[6], aptr8[6] + (ss) * 128);                     \
    CP_ASYNC16(buf + adst8[7], aptr8[7] + (ss) * 128);                     \
} while (0)

            RECW_ISSUE(0, 0); CP_COMMIT();
            RECW_ISSUE(1, 1); CP_COMMIT();
            RECW_ISSUE(2, 2); CP_COMMIT();

#pragma unroll 1
            for (int s = 0; s < NSTG; s++) {
                if (s + 3 < NSTG) { __syncwarp(); RECW_ISSUE(s + 3, (s + 3) & 3); }
                CP_COMMIT();
                CP_WAIT3();
                __syncwarp();

                const uint32_t aB = awbase + (uint32_t)(s & 3) * 4096u;

#pragma unroll
                for (int b = 0; b < 2; b++) {
                    const int u = 2 * s + b;
                    const bool hiseg = ((u >> 3) & 1) == 0;
                    const int ut0 = hiseg ? u : (u - 8);

                    uint32_t aR[4][4];
#pragma unroll
                    for (int kk = 0; kk < 4; kk++) {
                        int arow = lane & 15;
                        int ac   = kk * 2 + (lane >> 4);
                        LDMATRIX_X4(aR[kk][0], aR[kk][1], aR[kk][2], aR[kk][3],
                                    aB + (uint32_t)(b * 2048 + arow * 128 +
                                                    ((ac ^ (arow & 7)) << 4)));
                    }
                    const int ntgt = hiseg ? 2 : 1;
#pragma unroll
                    for (int tg_ = 0; tg_ < 2; tg_++) {
                        if (tg_ >= ntgt) break;
                        const int ut = (tg_ == 0) ? ut0 : (u + 8);
                        const uint32_t wB = sbase + (uint32_t)(ut * WBLK);
                        if (isL0) {
#pragma unroll
                            for (int kk = 0; kk < 4; kk++) {
                                int brow = (lane & 7) + ((lane >> 4) << 3);
                                int bc   = kk * 2 + ((lane >> 3) & 1);
                                uint32_t b0, b1r, b2, b3;
                                LDMATRIX_X4(b0, b1r, b2, b3,
                                            wB + (uint32_t)(brow * 128 +
                                                            ((bc ^ (brow & 7)) << 4)));
                                MMA16816(acc[0], aR[kk][0], aR[kk][1], aR[kk][2], aR[kk][3], b0, b1r);
                                MMA16816(acc[1], aR[kk][0], aR[kk][1], aR[kk][2], aR[kk][3], b2, b3);
                            }
                        } else {
#pragma unroll
                            for (int kk2 = 0; kk2 < 2; kk2++) {
                                int brow = lane & 7;
                                int bc   = kk2 * 4 + ((lane >> 3) & 3);
                                uint32_t b0, b1r, b2, b3;
                                LDMATRIX_X4(b0, b1r, b2, b3,
                                            wB + (uint32_t)(brow * 128 +
                                                            ((bc ^ (brow & 7)) << 4)));
                                MMA16816(acc[0], aR[kk2*2][0],   aR[kk2*2][1],   aR[kk2*2][2],   aR[kk2*2][3],   b0, b1r);
                                MMA16816(acc[0], aR[kk2*2+1][0], aR[kk2*2+1][1], aR[kk2*2+1][2], aR[kk2*2+1][3], b2, b3);
                            }
                        }
                    }
                }
            }

            // ---------------- epilogue ----------------
            const int g = lane >> 2, tg = lane & 3;
            if (isL0) {
                const float* A0t = g_A0 + (size_t)t * BATCH * HID;
                __half* l0n  = g_L0A + (size_t)(t + 1) * BATCH * 1024;
                __half* l1h0 = g_L1A + (size_t)t * BATCH * 2048;
#pragma unroll
                for (int j = 0; j < 2; j++) {          // two n8 tiles
                    int col = nbase + j * 8 + tg * 2;
#pragma unroll
                    for (int h = 0; h < 2; h++) {
                        int brow = w * 16 + g + h * 8;
                        float2 a0v = *(const float2*)&A0t[(size_t)brow * 512 + col];
                        float x0 = tanhf(acc[j][h * 2 + 0] + a0v.x);
                        float x1 = tanhf(acc[j][h * 2 + 1] + a0v.y);
                        __half h0 = __float2half_rn(x0), h1 = __float2half_rn(x1);
                        __half l0 = __float2half_rn(x0 - __half2float(h0));
                        __half l1 = __float2half_rn(x1 - __half2float(h1));
                        __half2 hi2 = __halves2half2(h0, h1);
                        __half2 lo2 = __halves2half2(l0, l1);
                        size_t r0 = (size_t)brow * 1024;
                        *(__half2*)&l0n[r0 + col]       = hi2;
                        *(__half2*)&l0n[r0 + 512 + col] = lo2;
                        size_t r1 = (size_t)brow * 2048;
                        *(__half2*)&l1h0[r1 + col]       = hi2;
                        *(__half2*)&l1h0[r1 + 512 + col] = lo2;
                        if (t == S_LEN - 1)
                            *(float2*)&g_H0[((size_t)t * BATCH + brow) * 512 + col] =
                                make_float2(x0, x1);
                    }
                }
            } else {
                __half* l1n = g_L1A + (size_t)(t + 1) * BATCH * 2048;
                int col = nbase + tg * 2;
                float2 bv = *(const float2*)&b1[col];
#pragma unroll
                for (int h = 0; h < 2; h++) {
                    int brow = w * 16 + g + h * 8;
                    float x0 = tanhf(acc[0][h * 2 + 0] + bv.x);
                    float x1 = tanhf(acc[0][h * 2 + 1] + bv.y);
                    __half h0 = __float2half_rn(x0), h1 = __float2half_rn(x1);
                    __half l0 = __float2half_rn(x0 - __half2float(h0));
                    __half l1 = __float2half_rn(x1 - __half2float(h1));
                    __half2 hi2 = __halves2half2(h0, h1);
                    __half2 lo2 = __halves2half2(l0, l1);
                    size_t r1 = (size_t)brow * 2048;
                    *(__half2*)&l1n[r1 + 1024 + col] = hi2;
                    *(__half2*)&l1n[r1 + 1536 + col] = lo2;
                    *(__half2*)&g_H1H[((size_t)t * BATCH + brow) * 512 + col] = hi2;
                    if (t == S_LEN - 1)
                        *(float2*)&g_H1[((size_t)t * BATCH + brow) * 512 + col] =
                            make_float2(x0, x1);
                }
            }
        }

        // grid barrier (proven)
        if (p < S_LEN) {
            __syncthreads();
            __threadfence();
            if (tid == 0) {
                atomicAdd(&g_arrive, 1u);
                unsigned target = (unsigned)REC_CTAS * (unsigned)(p + 1);
                unsigned v;
                do {
                    asm volatile("ld.acquire.gpu.global.u32 %0, [%1];"
                                 : "=r"(v) : "l"(&g_arrive));
                } while (v < target);
            }
            __syncthreads();
        }
    }
}

// ---------------------------------------------------------------------------
__global__ void copy_hidden_kernel(float* __restrict__ dst)
{
    const int BH = BATCH * HID;
    int i = blockIdx.x * blockDim.x + threadIdx.x;
    if (i < BH)           dst[i] = g_H0[(size_t)(S_LEN - 1) * BH + i];
    else if (i < 2 * BH)  dst[i] = g_H1[(size_t)(S_LEN - 1) * BH + (i - BH)];
}

// ---------------------------------------------------------------------------
extern "C" void kernel_launch(void* const* d_in, const int* in_sizes, int n_in,
                              void* d_out, int out_size)
{
    const int*   inputs = (const int*)  d_in[0];
    const float* hidden = (const float*)d_in[1];
    const float* emb    = (const float*)d_in[2];
    const float* W0     = (const float*)d_in[3];
    const float* b0     = (const float*)d_in[4];
    const float* W1     = (const float*)d_in[5];
    const float* b1     = (const float*)d_in[6];
    const float* Wout   = (const float*)d_in[7];
    const float* bout   = (const float*)d_in[8];
    float* out = (float*)d_out;

    cudaFuncSetAttribute(gemm_fp16_mma, cudaFuncAttributeMaxDynamicSharedMemorySize,
                         GEMM_SMEM);
    cudaFuncSetAttribute(rnn_rec_tc, cudaFuncAttributeMaxDynamicSharedMemorySize,
                         REC_SMEM);

    __half *embS, *w0xS, *woutH, *h1H, *w0hS, *w1S, *l0a, *l1a;
    float *a0;
    cudaGetSymbolAddress((void**)&embS,  g_embS);
    cudaGetSymbolAddress((void**)&w0xS,  g_W0xS);
    cudaGetSymbolAddress((void**)&woutH, g_WoutH);
    cudaGetSymbolAddress((void**)&h1H,   g_H1H);
    cudaGetSymbolAddress((void**)&w0hS,  g_W0hS);
    cudaGetSymbolAddress((void**)&w1S,   g_W1S);
    cudaGetSymbolAddress((void**)&l0a,   g_L0A);
    cudaGetSymbolAddress((void**)&l1a,   g_L1A);
    cudaGetSymbolAddress((void**)&a0,    g_A0);

    const int BH = BATCH * HID;

    reset_barrier_kernel<<<1, 1>>>();

    split_half_ld<<<(VOCAB * 512 + 255) / 256, 256>>>(emb, 512, VOCAB, embS, 1536, 0, VOCAB, 0);
    split_half_ld<<<(HID * 512 + 255) / 256, 256>>>(W0,       1024, HID, w0xS, 1536, 0,    HID, 1);
    split_half_ld<<<(HID * 512 + 255) / 256, 256>>>(W0 + 512, 1024, HID, w0hS, 1024, 0,    HID, 2);
    split_half_ld<<<(HID * 512 + 255) / 256, 256>>>(W1,       1024, HID, w1S,  2048, 0,    HID, 2);
    split_half_ld<<<(HID * 512 + 255) / 256, 256>>>(W1 + 512, 1024, HID, w1S,  2048, 1024, HID, 2);
    to_half_kernel<<<(NPAD * 512 + 255) / 256, 256>>>(Wout, 512, VOCAB, woutH, NPAD);
    split_half_ld<<<(BATCH * 512 + 255) / 256, 256>>>(hidden,      512, BATCH, l0a, 1024, 0,    BATCH, 2);
    split_half_ld<<<(BATCH * 512 + 255) / 256, 256>>>(hidden + BH, 512, BATCH, l1a, 2048, 1024, BATCH, 2);

    {
        dim3 grid(HID / 128, (S_LEN * BATCH) / 128);
        gemm_fp16_mma<<<grid, 256, GEMM_SMEM>>>(embS, inputs, w0xS, b0, a0, HID, HID, 1536);
    }

    rnn_rec_tc<<<REC_CTAS, 256, REC_SMEM>>>(b1);

    {
        dim3 grid(NPAD / 128, (S_LEN * BATCH) / 128);
        gemm_fp16_mma<<<grid, 256, GEMM_SMEM>>>(h1H, nullptr, woutH, bout, out, VOCAB,
                                                VOCAB, 512);
    }

    long long need = (long long)S_LEN * BATCH * VOCAB + 2LL * BATCH * HID;
    if ((long long)out_size >= need) {
        float* tail = out + (size_t)S_LEN * BATCH * VOCAB;
        copy_hidden_kernel<<<(2 * BATCH * HID) / 256, 256>>>(tail);
    }
}